// round 7
// baseline (speedup 1.0000x reference)
#include <cuda_runtime.h>
#include <math.h>

#define H_IN 321
#define W_IN 321
#define WS 41
#define NPIX 1681
#define NCH 21
#define CP 24
#define NBATCH 16
#define NITERS 10

#define INVSC (321.0f/41.0f)
#define AG 8.0f                 /* 1/(2*(3/12)^2) */
#define SA 0.10606601718f       /* sqrt(ABF), ABF=0.01125 */
#define SB 0.05439282932f       /* sqrt(1/338) */
#define CG 3.0f
#define CB 10.0f
#define EPSV 1e-5f

#define KSTRIDE 1684            /* padded fp32 K row stride */
#define KSPLIT 4
#define KSEG 421
#define TILE_M 128
#define KCH2 32
#define TI 16                   /* k_keff i-tile */
#define NLB 64

__device__ __forceinline__ int div41(int j) { return (j*51151) >> 21; }

// ---------------- static device buffers ----------------
static __device__ float  g_feat[NBATCH*NPIX*8];   // ax,ay,br,bg,bb,nrm,x,y
static __device__ float  g_rsg[NPIX];
static __device__ float  g_rsb[NBATCH*NPIX];
static __device__ float  g_probs[NBATCH*NPIX*CP];
static __device__ float  g_logu[NBATCH*NPIX*CP];
static __device__ float  g_Qa[NBATCH*NPIX*CP];
static __device__ float  g_Qb[NBATCH*NPIX*CP];
static __device__ float  g_part[(size_t)KSPLIT*NBATCH*NPIX*CP];
static __device__ float  g_lpart[NLB];
static __device__ float  g_K[(size_t)NBATCH*NPIX*KSTRIDE + 256];

// ---------------- setup ----------------

__global__ void k_rsg() {
    int i = blockIdx.x*blockDim.x + threadIdx.x;
    if (i >= NPIX) return;
    int y = div41(i), x = i - y*41;
    float Sx = 0.f, Sy = 0.f;
    for (int j = 0; j < WS; j++) {
        int dx = x - j; Sx += expf(-AG * (float)(dx*dx));
        int dy = y - j; Sy += expf(-AG * (float)(dy*dy));
    }
    g_rsg[i] = rsqrtf(Sx*Sy - 1.0f);
}

// resize (jax linear/antialias, scale 321/41) -> feature vectors
__global__ void k_resize(const float* __restrict__ img) {
    int t = blockIdx.x*blockDim.x + threadIdx.x;
    if (t >= NBATCH*NPIX) return;
    int n = t / NPIX, p = t - n*NPIX;
    int oy = div41(p), ox = p - oy*41;

    float wy[18], wx[18];
    float sy = (oy + 0.5f)*INVSC - 0.5f;
    int jy0 = max(0, (int)ceilf(sy - INVSC));
    int jy1 = min(H_IN-1, (int)floorf(sy + INVSC));
    float sumy = 0.f;
    for (int j = jy0; j <= jy1; j++) {
        float w = fmaxf(1.0f - fabsf(sy - (float)j)*(1.0f/INVSC), 0.f);
        wy[j-jy0] = w; sumy += w;
    }
    float sx = (ox + 0.5f)*INVSC - 0.5f;
    int jx0 = max(0, (int)ceilf(sx - INVSC));
    int jx1 = min(W_IN-1, (int)floorf(sx + INVSC));
    float sumx = 0.f;
    for (int j = jx0; j <= jx1; j++) {
        float w = fmaxf(1.0f - fabsf(sx - (float)j)*(1.0f/INVSC), 0.f);
        wx[j-jx0] = w; sumx += w;
    }

    float a0 = 0.f, a1 = 0.f, a2 = 0.f;
    const float* b0 = img + (size_t)(n*3 + 0)*H_IN*W_IN;
    const float* b1 = img + (size_t)(n*3 + 1)*H_IN*W_IN;
    const float* b2 = img + (size_t)(n*3 + 2)*H_IN*W_IN;
    for (int jy = jy0; jy <= jy1; jy++) {
        float wyv = wy[jy-jy0];
        const float* r0 = b0 + (size_t)jy*W_IN;
        const float* r1 = b1 + (size_t)jy*W_IN;
        const float* r2 = b2 + (size_t)jy*W_IN;
        for (int jx = jx0; jx <= jx1; jx++) {
            float w = wyv * wx[jx-jx0];
            a0 = fmaf(w, r0[jx], a0);
            a1 = fmaf(w, r1[jx], a1);
            a2 = fmaf(w, r2[jx], a2);
        }
    }
    float inv = 1.0f/(sumy*sumx);
    float fx = (float)ox, fy = (float)oy;
    float ax = fx*SA, ay = fy*SA;
    float br = a0*inv*SB, bg = a1*inv*SB, bb = a2*inv*SB;
    float nrm = ax*ax + ay*ay + br*br + bg*bg + bb*bb;
    float4* F = (float4*)(g_feat + (size_t)t*8);
    F[0] = make_float4(ax, ay, br, bg);
    F[1] = make_float4(bb, nrm, fx, fy);
}

__global__ void k_probs(const float* __restrict__ pred) {
    int t = blockIdx.x*blockDim.x + threadIdx.x;
    if (t >= NBATCH*NPIX) return;
    int n = t / NPIX, p = t - n*NPIX;
    const float* base = pred + (size_t)n*NCH*NPIX + p;
    float x[NCH];
    float m = -1e30f;
    #pragma unroll
    for (int c = 0; c < NCH; c++) { x[c] = base[(size_t)c*NPIX]; m = fmaxf(m, x[c]); }
    float s = 0.f;
    #pragma unroll
    for (int c = 0; c < NCH; c++) { x[c] = __expf(x[c]-m); s += x[c]; }
    float inv = 1.0f/s;
    float s2 = 0.f;
    #pragma unroll
    for (int c = 0; c < NCH; c++) { x[c] = fminf(fmaxf(x[c]*inv, EPSV), 1.0f); s2 += x[c]; }
    float inv2 = 1.0f/s2;
    float* pp = g_probs + (size_t)t*CP;
    float* pl = g_logu  + (size_t)t*CP;
    float* pq = g_Qa    + (size_t)t*CP;
    #pragma unroll
    for (int c = 0; c < NCH; c++) {
        float v = x[c]*inv2;
        pp[c] = v; pl[c] = __logf(v); pq[c] = v;
    }
    #pragma unroll
    for (int c = NCH; c < CP; c++) { pp[c] = 0.f; pl[c] = 0.f; pq[c] = 0.f; }
}

// bilateral row sums: thread-per-i, j-features staged through smem (broadcast)
#define SJC 128
__global__ void __launch_bounds__(256) k_sums() {
    __shared__ float4 Fs[SJC*2];
    int n = blockIdx.y;
    int i = blockIdx.x*256 + threadIdx.x;
    int ic = min(i, NPIX-1);
    const float4* F = (const float4*)(g_feat + (size_t)(n*NPIX)*8);
    float4 fa = F[2*ic], fb = F[2*ic+1];
    float f0 = 2.f*fa.x, f1 = 2.f*fa.y, f2 = 2.f*fa.z, f3 = 2.f*fa.w, f4 = 2.f*fb.x;
    float ni = fb.y;
    float sum = 0.f;
    for (int j0 = 0; j0 < NPIX; j0 += SJC) {
        int jc = min(SJC, NPIX - j0);
        __syncthreads();
        if (threadIdx.x < 2*jc) Fs[threadIdx.x] = F[2*j0 + threadIdx.x];
        __syncthreads();
        for (int j = 0; j < jc; j++) {
            float4 ja = Fs[2*j], jb = Fs[2*j+1];
            float e = -ni - jb.y;
            e = fmaf(f0, ja.x, e); e = fmaf(f1, ja.y, e); e = fmaf(f2, ja.z, e);
            e = fmaf(f3, ja.w, e); e = fmaf(f4, jb.x, e);
            sum += __expf(e);
        }
    }
    if (i < NPIX) g_rsb[n*NPIX + i] = rsqrtf(sum - 1.0f);  // self term exp(0)=1
}

// fused Keff = 10*Kb_norm + 3*Kg_norm, diag 0, fp32, i-tiled x16
__global__ void __launch_bounds__(256) k_keff() {
    __shared__ float4 Fi[TI*2];
    __shared__ float Ri[TI];   // rsb[i]
    __shared__ float Gi[TI];   // rsg[i]
    int n = blockIdx.z;
    int it0 = blockIdx.y*TI;
    int j = blockIdx.x*256 + threadIdx.x;
    int jcl = min(j, NPIX-1);
    const float4* F = (const float4*)(g_feat + (size_t)(n*NPIX)*8);
    const float* rsb = g_rsb + n*NPIX;

    if (threadIdx.x < TI) {
        int ii = min(it0 + threadIdx.x, NPIX-1);
        Fi[2*threadIdx.x]   = F[2*ii];
        Fi[2*threadIdx.x+1] = F[2*ii+1];
        Ri[threadIdx.x] = rsb[ii];
        Gi[threadIdx.x] = g_rsg[ii];
    }
    __syncthreads();

    // j-side features in registers
    float4 ja = F[2*jcl], jb = F[2*jcl+1];
    float rsbj = rsb[jcl], rsgj = g_rsg[jcl];
    float nj = jb.y, xj = jb.z, yj = jb.w;
    float* Kbase = g_K + (size_t)(n*NPIX)*KSTRIDE + j;

    #pragma unroll 4
    for (int ii = 0; ii < TI; ii++) {
        int i = it0 + ii;
        if (i >= NPIX) break;
        float4 fa = Fi[2*ii], fb = Fi[2*ii+1];
        float e = -fb.y - nj;
        e = fmaf(2.f*fa.x, ja.x, e); e = fmaf(2.f*fa.y, ja.y, e);
        e = fmaf(2.f*fa.z, ja.z, e); e = fmaf(2.f*fa.w, ja.w, e);
        e = fmaf(2.f*fb.x, jb.x, e);
        float v = CB * __expf(e) * Ri[ii] * rsbj;
        float dx = fb.z - xj, dy = fb.w - yj;
        float d2 = fmaf(dx, dx, dy*dy);
        if (d2 < 12.5f) v = fmaf(CG, __expf(-AG*d2)*Gi[ii]*rsgj, v);
        if (j == i) v = 0.f;
        if (j < NPIX) Kbase[(size_t)i*KSTRIDE] = v;
    }
}

// ---------------- mean-field msg GEMM ----------------
// part[kz][n][row][c] = sum_{k in seg} K[k][row] * Q[k][c]   (K symmetric, fp32)
// thread tile: 4 rows (2 f32x2 pairs) x 6 channels; Q pre-duplicated in smem.
__global__ void __launch_bounds__(128) k_msg(int dir) {
    __shared__ float Kt[KCH2][TILE_M];     // 16 KB
    __shared__ float Qt2[KCH2][48];        // 6 KB duplicated Q pairs
    const float* Qin = dir ? g_Qb : g_Qa;
    int n = blockIdx.z, kz = blockIdx.y;
    int rowbase = blockIdx.x * TILE_M;
    int tid = threadIdx.x;
    int ng = tid & 3, mg = tid >> 2;       // ng: 6-ch group, mg: 4-row group
    int kbase = kz*KSEG, kend = min(NPIX, kbase + KSEG);
    const float* __restrict__ Qn = Qin + (size_t)n*NPIX*CP;
    const float* __restrict__ Kn = g_K + (size_t)n*NPIX*KSTRIDE;

    unsigned long long a[12];
    #pragma unroll
    for (int u = 0; u < 12; u++) a[u] = 0ull;

    for (int k0 = kbase; k0 < kend; k0 += KCH2) {
        int kc = min(KCH2, kend - k0);
        // stage K tile (coalesced float4; row overread lands in padded/valid mem)
        for (int idx = tid; idx < kc*(TILE_M/4); idx += 128) {
            int kk = idx >> 5, r4 = idx & 31;
            *(float4*)&Kt[kk][r4*4] =
                *(const float4*)(Kn + (size_t)(k0+kk)*KSTRIDE + rowbase + r4*4);
        }
        // stage Q duplicated: {q,q} pairs
        for (int idx = tid; idx < kc*6; idx += 128) {
            int kk = idx / 6, f4 = idx - kk*6;
            float4 v = *((const float4*)(Qn + (size_t)(k0+kk)*CP) + f4);
            *(float4*)&Qt2[kk][8*f4]     = make_float4(v.x, v.x, v.y, v.y);
            *(float4*)&Qt2[kk][8*f4 + 4] = make_float4(v.z, v.z, v.w, v.w);
        }
        __syncthreads();
        #pragma unroll 4
        for (int kk = 0; kk < kc; kk++) {
            ulonglong2 kp = *(const ulonglong2*)&Kt[kk][mg*4];
            const ulonglong2* qp = (const ulonglong2*)&Qt2[kk][ng*12];
            ulonglong2 qA = qp[0], qB = qp[1], qC = qp[2];
            asm("fma.rn.f32x2 %0, %1, %2, %0;" : "+l"(a[0])  : "l"(kp.x), "l"(qA.x));
            asm("fma.rn.f32x2 %0, %1, %2, %0;" : "+l"(a[1])  : "l"(kp.x), "l"(qA.y));
            asm("fma.rn.f32x2 %0, %1, %2, %0;" : "+l"(a[2])  : "l"(kp.x), "l"(qB.x));
            asm("fma.rn.f32x2 %0, %1, %2, %0;" : "+l"(a[3])  : "l"(kp.x), "l"(qB.y));
            asm("fma.rn.f32x2 %0, %1, %2, %0;" : "+l"(a[4])  : "l"(kp.x), "l"(qC.x));
            asm("fma.rn.f32x2 %0, %1, %2, %0;" : "+l"(a[5])  : "l"(kp.x), "l"(qC.y));
            asm("fma.rn.f32x2 %0, %1, %2, %0;" : "+l"(a[6])  : "l"(kp.y), "l"(qA.x));
            asm("fma.rn.f32x2 %0, %1, %2, %0;" : "+l"(a[7])  : "l"(kp.y), "l"(qA.y));
            asm("fma.rn.f32x2 %0, %1, %2, %0;" : "+l"(a[8])  : "l"(kp.y), "l"(qB.x));
            asm("fma.rn.f32x2 %0, %1, %2, %0;" : "+l"(a[9])  : "l"(kp.y), "l"(qB.y));
            asm("fma.rn.f32x2 %0, %1, %2, %0;" : "+l"(a[10]) : "l"(kp.y), "l"(qC.x));
            asm("fma.rn.f32x2 %0, %1, %2, %0;" : "+l"(a[11]) : "l"(kp.y), "l"(qC.y));
        }
        __syncthreads();
    }

    // a[rp*6 + c] = {row mg*4+2rp+0 (lo), row mg*4+2rp+1 (hi)}
    float* pb = g_part + (((size_t)kz*NBATCH + n)*NPIX)*CP;
    #pragma unroll
    for (int rp = 0; rp < 2; rp++) {
        float lo[6], hi[6];
        #pragma unroll
        for (int c = 0; c < 6; c++)
            asm("mov.b64 {%0,%1}, %2;" : "=f"(lo[c]), "=f"(hi[c]) : "l"(a[rp*6+c]));
        int r0 = rowbase + mg*4 + 2*rp;
        if (r0 < NPIX) {
            float* o = pb + (size_t)r0*CP + ng*6;
            *(float2*)(o)   = make_float2(lo[0], lo[1]);
            *(float2*)(o+2) = make_float2(lo[2], lo[3]);
            *(float2*)(o+4) = make_float2(lo[4], lo[5]);
        }
        if (r0 + 1 < NPIX) {
            float* o = pb + (size_t)(r0+1)*CP + ng*6;
            *(float2*)(o)   = make_float2(hi[0], hi[1]);
            *(float2*)(o+2) = make_float2(hi[2], hi[3]);
            *(float2*)(o+4) = make_float2(hi[4], hi[5]);
        }
    }
}

// combine partials + softmax with logu
__global__ void k_update(int dir) {
    int t = blockIdx.x*blockDim.x + threadIdx.x;
    if (t >= NBATCH*NPIX) return;
    float* Qout = dir ? g_Qa : g_Qb;
    const float* lg = g_logu + (size_t)t*CP;
    const float* p0 = g_part + (size_t)t*CP;
    const float* p1 = p0 + (size_t)NBATCH*NPIX*CP;
    const float* p2 = p1 + (size_t)NBATCH*NPIX*CP;
    const float* p3 = p2 + (size_t)NBATCH*NPIX*CP;
    float lt[NCH];
    float m = -1e30f;
    #pragma unroll
    for (int c = 0; c < NCH; c++) {
        lt[c] = lg[c] + ((p0[c] + p1[c]) + (p2[c] + p3[c]));
        m = fmaxf(m, lt[c]);
    }
    float s = 0.f;
    #pragma unroll
    for (int c = 0; c < NCH; c++) { lt[c] = __expf(lt[c]-m); s += lt[c]; }
    float inv = 1.0f/s;
    float* o = Qout + (size_t)t*CP;
    #pragma unroll
    for (int c = 0; c < NCH; c++) o[c] = lt[c]*inv;
    o[21] = 0.f; o[22] = 0.f; o[23] = 0.f;
}

// ---------------- loss ----------------
__global__ void k_loss1() {
    int tid = threadIdx.x;
    float part = 0.f;
    for (int t = blockIdx.x*256 + tid; t < NBATCH*NPIX; t += NLB*256) {
        const float* q  = g_Qa    + (size_t)t*CP;
        const float* pr = g_probs + (size_t)t*CP;
        float ps[NCH];
        float s = 0.f;
        #pragma unroll
        for (int c = 0; c < NCH; c++) { ps[c] = fmaxf(q[c], EPSV); s += ps[c]; }
        float inv = 1.0f/s;
        #pragma unroll
        for (int c = 0; c < NCH; c++) {
            float p = ps[c]*inv;
            float r = p/pr[c];
            r = fminf(fmaxf(r, 0.05f), 20.0f);
            part += p*__logf(r);
        }
    }
    for (int o = 16; o; o >>= 1) part += __shfl_down_sync(0xffffffffu, part, o);
    __shared__ float red[8];
    int wid = tid >> 5, lane = tid & 31;
    if (lane == 0) red[wid] = part;
    __syncthreads();
    if (wid == 0) {
        float v = (lane < 8) ? red[lane] : 0.f;
        for (int o = 4; o; o >>= 1) v += __shfl_down_sync(0xffffffffu, v, o);
        if (lane == 0) g_lpart[blockIdx.x] = v;
    }
}

__global__ void k_loss2(float* __restrict__ out) {
    int lane = threadIdx.x;   // 64 threads
    float v = g_lpart[lane];
    for (int o = 16; o; o >>= 1) v += __shfl_down_sync(0xffffffffu, v, o);
    __shared__ float red[2];
    if ((lane & 31) == 0) red[lane >> 5] = v;
    __syncthreads();
    if (lane == 0) out[0] = (red[0] + red[1]) / (float)(NBATCH*NPIX);
}

extern "C" void kernel_launch(void* const* d_in, const int* in_sizes, int n_in,
                              void* d_out, int out_size) {
    const float* images  = (const float*)d_in[0];
    const float* predict = (const float*)d_in[1];
    if (n_in >= 2 && in_sizes[0] < in_sizes[1]) {
        const float* tmp = images; images = predict; predict = tmp;
    }

    k_rsg<<<(NPIX + 255)/256, 256>>>();
    k_resize<<<(NBATCH*NPIX + 127)/128, 128>>>(images);
    k_probs<<<(NBATCH*NPIX + 127)/128, 128>>>(predict);
    k_sums<<<dim3((NPIX + 255)/256, NBATCH), 256>>>();
    k_keff<<<dim3((NPIX + 255)/256, (NPIX + TI - 1)/TI, NBATCH), 256>>>();
    for (int it = 0; it < NITERS; it++) {
        int dir = it & 1;
        k_msg<<<dim3((NPIX + TILE_M - 1)/TILE_M, KSPLIT, NBATCH), 128>>>(dir);
        k_update<<<(NBATCH*NPIX + 127)/128, 128>>>(dir);
    }
    k_loss1<<<NLB, 256>>>();
    k_loss2<<<1, 64>>>((float*)d_out);
}

// round 8
// speedup vs baseline: 1.9398x; 1.9398x over previous
#include <cuda_runtime.h>
#include <math.h>

#define H_IN 321
#define W_IN 321
#define WS 41
#define NPIX 1681
#define NCH 21
#define CP 24
#define NBATCH 16
#define NITERS 10

#define INVSC (321.0f/41.0f)
#define AG 8.0f                 /* 1/(2*(3/12)^2) */
#define ABF 0.011250f           /* 1/(2*(80/12)^2) */
#define BBF (1.0f/338.0f)       /* 1/(2*13^2) */
#define CG 3.0f
#define CB 10.0f
#define EPSV 1e-5f

#define KSTRIDE_H 1688          /* padded bf16 K row stride (x2B = 3376, 16B-aligned) */
#define KSPLIT 4
#define KSEG 421                /* ceil(1681/4) */
#define TILE_M 128
#define KCH2 32
#define NLB 64

// exact for 0 <= j < 2000: y = j/41
__device__ __forceinline__ int div41(int j) { return (j*51151) >> 21; }

// ---------------- static device buffers ----------------
static __device__ float  g_colors[NBATCH*NPIX*4];
static __device__ float2 g_pos[NPIX];
static __device__ float  g_rsg[NPIX];
static __device__ float  g_rsb[NBATCH*NPIX];
static __device__ float  g_probs[NBATCH*NPIX*CP];
static __device__ float  g_logu[NBATCH*NPIX*CP];
static __device__ float  g_Qa[NBATCH*NPIX*CP];
static __device__ float  g_Qb[NBATCH*NPIX*CP];
static __device__ float  g_part[(size_t)KSPLIT*NBATCH*NPIX*CP];
static __device__ float  g_lpart[NLB];
static __device__ unsigned short g_Kh[(size_t)NBATCH*NPIX*KSTRIDE_H + 4096]; // bf16 Keff

// ---------------- setup ----------------

__global__ void k_rsg() {
    int i = blockIdx.x*blockDim.x + threadIdx.x;
    if (i >= NPIX) return;
    int y = div41(i), x = i - y*41;
    g_pos[i] = make_float2((float)x, (float)y);
    float Sx = 0.f, Sy = 0.f;
    for (int j = 0; j < WS; j++) {
        int dx = x - j; Sx += expf(-AG * (float)(dx*dx));
        int dy = y - j; Sy += expf(-AG * (float)(dy*dy));
    }
    g_rsg[i] = rsqrtf(Sx*Sy - 1.0f);
}

__global__ void k_resize(const float* __restrict__ img) {
    int t = blockIdx.x*blockDim.x + threadIdx.x;
    if (t >= NBATCH*NPIX) return;
    int n = t / NPIX, p = t - n*NPIX;
    int oy = div41(p), ox = p - oy*41;

    float wy[18], wx[18];
    float sy = (oy + 0.5f)*INVSC - 0.5f;
    int jy0 = max(0, (int)ceilf(sy - INVSC));
    int jy1 = min(H_IN-1, (int)floorf(sy + INVSC));
    float sumy = 0.f;
    for (int j = jy0; j <= jy1; j++) {
        float w = fmaxf(1.0f - fabsf(sy - (float)j)*(1.0f/INVSC), 0.f);
        wy[j-jy0] = w; sumy += w;
    }
    float sx = (ox + 0.5f)*INVSC - 0.5f;
    int jx0 = max(0, (int)ceilf(sx - INVSC));
    int jx1 = min(W_IN-1, (int)floorf(sx + INVSC));
    float sumx = 0.f;
    for (int j = jx0; j <= jx1; j++) {
        float w = fmaxf(1.0f - fabsf(sx - (float)j)*(1.0f/INVSC), 0.f);
        wx[j-jx0] = w; sumx += w;
    }

    float a0 = 0.f, a1 = 0.f, a2 = 0.f;
    const float* b0 = img + (size_t)(n*3 + 0)*H_IN*W_IN;
    const float* b1 = img + (size_t)(n*3 + 1)*H_IN*W_IN;
    const float* b2 = img + (size_t)(n*3 + 2)*H_IN*W_IN;
    for (int jy = jy0; jy <= jy1; jy++) {
        float wyv = wy[jy-jy0];
        const float* r0 = b0 + (size_t)jy*W_IN;
        const float* r1 = b1 + (size_t)jy*W_IN;
        const float* r2 = b2 + (size_t)jy*W_IN;
        for (int jx = jx0; jx <= jx1; jx++) {
            float w = wyv * wx[jx-jx0];
            a0 = fmaf(w, r0[jx], a0);
            a1 = fmaf(w, r1[jx], a1);
            a2 = fmaf(w, r2[jx], a2);
        }
    }
    float inv = 1.0f/(sumy*sumx);
    float4 c; c.x = a0*inv; c.y = a1*inv; c.z = a2*inv; c.w = 0.f;
    ((float4*)g_colors)[t] = c;
}

__global__ void k_probs(const float* __restrict__ pred) {
    int t = blockIdx.x*blockDim.x + threadIdx.x;
    if (t >= NBATCH*NPIX) return;
    int n = t / NPIX, p = t - n*NPIX;
    const float* base = pred + (size_t)n*NCH*NPIX + p;
    float x[NCH];
    float m = -1e30f;
    #pragma unroll
    for (int c = 0; c < NCH; c++) { x[c] = base[(size_t)c*NPIX]; m = fmaxf(m, x[c]); }
    float s = 0.f;
    #pragma unroll
    for (int c = 0; c < NCH; c++) { x[c] = __expf(x[c]-m); s += x[c]; }
    float inv = 1.0f/s;
    float s2 = 0.f;
    #pragma unroll
    for (int c = 0; c < NCH; c++) { x[c] = fminf(fmaxf(x[c]*inv, EPSV), 1.0f); s2 += x[c]; }
    float inv2 = 1.0f/s2;
    float* pp = g_probs + (size_t)t*CP;
    float* pl = g_logu  + (size_t)t*CP;
    float* pq = g_Qa    + (size_t)t*CP;
    #pragma unroll
    for (int c = 0; c < NCH; c++) {
        float v = x[c]*inv2;
        pp[c] = v; pl[c] = __logf(v); pq[c] = v;
    }
    #pragma unroll
    for (int c = NCH; c < CP; c++) { pp[c] = 0.f; pl[c] = 0.f; pq[c] = 0.f; }
}

// bilateral row sums (self term included -> subtract 1)   [R4 exact]
__global__ void k_sums() {
    int i = blockIdx.x, n = blockIdx.y;
    int tid = threadIdx.x;
    const float4* cols = ((const float4*)g_colors) + (size_t)n*NPIX;
    float4 ci = cols[i];
    float2 pi = g_pos[i];
    float sum = 0.f;
    for (int j = tid; j < NPIX; j += 256) {
        float2 pj = g_pos[j];
        float4 cj = cols[j];
        float dy = pi.y - pj.y, dx = pi.x - pj.x;
        float dr = ci.x - cj.x, dg = ci.y - cj.y, db = ci.z - cj.z;
        float d2 = fmaf(dy, dy, dx*dx);
        float cd2 = fmaf(dr, dr, fmaf(dg, dg, db*db));
        sum += __expf(fmaf(-ABF, d2, -BBF*cd2));
    }
    for (int o = 16; o; o >>= 1) sum += __shfl_down_sync(0xffffffffu, sum, o);
    __shared__ float red[8];
    int wid = tid >> 5, lane = tid & 31;
    if (lane == 0) red[wid] = sum;
    __syncthreads();
    if (wid == 0) {
        float v = (lane < 8) ? red[lane] : 0.f;
        for (int o = 4; o; o >>= 1) v += __shfl_down_sync(0xffffffffu, v, o);
        if (lane == 0) g_rsb[n*NPIX + i] = rsqrtf(v - 1.0f);
    }
}

// fused Keff = 10*Kb_norm + 3*Kg_norm, diag 0  [R4 math; ONLY change: bf16 store]
__global__ void k_keff() {
    int j = blockIdx.x*blockDim.x + threadIdx.x;
    if (j >= NPIX) return;
    int i = blockIdx.y, n = blockIdx.z;
    const float4* cols = ((const float4*)g_colors) + (size_t)n*NPIX;
    float4 ci = cols[i];
    float4 cj = cols[j];
    float2 pi = g_pos[i];
    float2 pj = g_pos[j];
    float dy = pi.y - pj.y, dx = pi.x - pj.x;
    float dr = ci.x - cj.x, dg = ci.y - cj.y, db = ci.z - cj.z;
    float d2 = fmaf(dy, dy, dx*dx);
    float cd2 = fmaf(dr, dr, fmaf(dg, dg, db*db));
    float kb = __expf(fmaf(-ABF, d2, -BBF*cd2)) * g_rsb[n*NPIX + i] * g_rsb[n*NPIX + j];
    float kg = __expf(-AG * d2) * g_rsg[i] * g_rsg[j];
    float v = fmaf(CB, kb, CG*kg);
    if (j == i) v = 0.f;
    unsigned int b;
    asm("cvt.rn.bf16x2.f32 %0, %1, %2;" : "=r"(b) : "f"(0.f), "f"(v));  // low half = v
    g_Kh[((size_t)(n*NPIX + i))*KSTRIDE_H + j] = (unsigned short)(b & 0xffffu);
}

// ---------------- mean-field msg GEMM [R4 inner loop exact; bf16 K staging] ----------------
__global__ void __launch_bounds__(128) k_msg(int dir) {
    __shared__ float Kt[KCH2][TILE_M];   // 16 KB fp32 (expanded from bf16)
    __shared__ float Qt[KCH2][CP];       // 3 KB
    const float* Qin = dir ? g_Qb : g_Qa;
    int n = blockIdx.z, kz = blockIdx.y;
    int rowbase = blockIdx.x * TILE_M;
    int tid = threadIdx.x;
    int ng = tid & 3, mg = tid >> 2;     // ng: channel group (6 ch), mg: 4-row group
    int kbase = kz*KSEG, kend = min(NPIX, kbase + KSEG);
    const float* __restrict__ Qn = Qin + (size_t)n*NPIX*CP;
    const unsigned short* __restrict__ Kn = g_Kh + (size_t)n*NPIX*KSTRIDE_H;

    unsigned long long a00=0,a01=0,a02=0, a10=0,a11=0,a12=0,
                       a20=0,a21=0,a22=0, a30=0,a31=0,a32=0;

    for (int k0 = kbase; k0 < kend; k0 += KCH2) {
        int kc = min(KCH2, kend - k0);
        // stage K tile: bf16 -> fp32 via shift (overread lands in padded/next-row mem,
        // discarded at store because those rows >= NPIX)
        for (int idx = tid; idx < kc*(TILE_M/8); idx += 128) {
            int kk = idx >> 4, g8 = idx & 15;
            uint4 raw = *(const uint4*)(Kn + (size_t)(k0+kk)*KSTRIDE_H + rowbase + g8*8);
            float4 A, B;
            A.x = __uint_as_float(raw.x << 16); A.y = __uint_as_float(raw.x & 0xffff0000u);
            A.z = __uint_as_float(raw.y << 16); A.w = __uint_as_float(raw.y & 0xffff0000u);
            B.x = __uint_as_float(raw.z << 16); B.y = __uint_as_float(raw.z & 0xffff0000u);
            B.z = __uint_as_float(raw.w << 16); B.w = __uint_as_float(raw.w & 0xffff0000u);
            *(float4*)&Kt[kk][g8*8]     = A;
            *(float4*)&Kt[kk][g8*8 + 4] = B;
        }
        // stage Q tile (contiguous copy)
        for (int idx = tid; idx < kc*6; idx += 128)
            ((float4*)Qt)[idx] = *((const float4*)(Qn + (size_t)k0*CP) + idx);
        __syncthreads();
        #pragma unroll 4
        for (int kk = 0; kk < kc; kk++) {
            float4 kv = *(const float4*)&Kt[kk][mg*4];
            const float* qb = &Qt[kk][ng*6];
            unsigned long long q0 = *(const unsigned long long*)(qb);
            unsigned long long q1 = *(const unsigned long long*)(qb+2);
            unsigned long long q2 = *(const unsigned long long*)(qb+4);
            unsigned long long k0d,k1d,k2d,k3d;
            unsigned int b0=__float_as_uint(kv.x), b1=__float_as_uint(kv.y);
            unsigned int b2=__float_as_uint(kv.z), b3=__float_as_uint(kv.w);
            asm("mov.b64 %0, {%1,%1};" : "=l"(k0d) : "r"(b0));
            asm("mov.b64 %0, {%1,%1};" : "=l"(k1d) : "r"(b1));
            asm("mov.b64 %0, {%1,%1};" : "=l"(k2d) : "r"(b2));
            asm("mov.b64 %0, {%1,%1};" : "=l"(k3d) : "r"(b3));
            asm("fma.rn.f32x2 %0, %1, %2, %0;" : "+l"(a00) : "l"(k0d), "l"(q0));
            asm("fma.rn.f32x2 %0, %1, %2, %0;" : "+l"(a01) : "l"(k0d), "l"(q1));
            asm("fma.rn.f32x2 %0, %1, %2, %0;" : "+l"(a02) : "l"(k0d), "l"(q2));
            asm("fma.rn.f32x2 %0, %1, %2, %0;" : "+l"(a10) : "l"(k1d), "l"(q0));
            asm("fma.rn.f32x2 %0, %1, %2, %0;" : "+l"(a11) : "l"(k1d), "l"(q1));
            asm("fma.rn.f32x2 %0, %1, %2, %0;" : "+l"(a12) : "l"(k1d), "l"(q2));
            asm("fma.rn.f32x2 %0, %1, %2, %0;" : "+l"(a20) : "l"(k2d), "l"(q0));
            asm("fma.rn.f32x2 %0, %1, %2, %0;" : "+l"(a21) : "l"(k2d), "l"(q1));
            asm("fma.rn.f32x2 %0, %1, %2, %0;" : "+l"(a22) : "l"(k2d), "l"(q2));
            asm("fma.rn.f32x2 %0, %1, %2, %0;" : "+l"(a30) : "l"(k3d), "l"(q0));
            asm("fma.rn.f32x2 %0, %1, %2, %0;" : "+l"(a31) : "l"(k3d), "l"(q1));
            asm("fma.rn.f32x2 %0, %1, %2, %0;" : "+l"(a32) : "l"(k3d), "l"(q2));
        }
        __syncthreads();
    }

    float* pb = g_part + (((size_t)kz*NBATCH + n)*NPIX)*CP;
    int r0 = rowbase + mg*4;
    unsigned long long* o;
    if (r0 + 0 < NPIX) { o = (unsigned long long*)(pb + (size_t)(r0+0)*CP + ng*6); o[0]=a00; o[1]=a01; o[2]=a02; }
    if (r0 + 1 < NPIX) { o = (unsigned long long*)(pb + (size_t)(r0+1)*CP + ng*6); o[0]=a10; o[1]=a11; o[2]=a12; }
    if (r0 + 2 < NPIX) { o = (unsigned long long*)(pb + (size_t)(r0+2)*CP + ng*6); o[0]=a20; o[1]=a21; o[2]=a22; }
    if (r0 + 3 < NPIX) { o = (unsigned long long*)(pb + (size_t)(r0+3)*CP + ng*6); o[0]=a30; o[1]=a31; o[2]=a32; }
}

// combine partials + softmax with logu  [R4 exact]
__global__ void k_update(int dir) {
    int t = blockIdx.x*blockDim.x + threadIdx.x;
    if (t >= NBATCH*NPIX) return;
    float* Qout = dir ? g_Qa : g_Qb;
    const float* lg = g_logu + (size_t)t*CP;
    const float* p0 = g_part + (size_t)t*CP;
    const float* p1 = p0 + (size_t)NBATCH*NPIX*CP;
    const float* p2 = p1 + (size_t)NBATCH*NPIX*CP;
    const float* p3 = p2 + (size_t)NBATCH*NPIX*CP;
    float lt[NCH];
    float m = -1e30f;
    #pragma unroll
    for (int c = 0; c < NCH; c++) {
        lt[c] = lg[c] + ((p0[c] + p1[c]) + (p2[c] + p3[c]));
        m = fmaxf(m, lt[c]);
    }
    float s = 0.f;
    #pragma unroll
    for (int c = 0; c < NCH; c++) { lt[c] = __expf(lt[c]-m); s += lt[c]; }
    float inv = 1.0f/s;
    float* o = Qout + (size_t)t*CP;
    #pragma unroll
    for (int c = 0; c < NCH; c++) o[c] = lt[c]*inv;
    o[21] = 0.f; o[22] = 0.f; o[23] = 0.f;
}

// ---------------- loss ----------------  [R4 exact]
__global__ void k_loss1() {
    int tid = threadIdx.x;
    float part = 0.f;
    for (int t = blockIdx.x*256 + tid; t < NBATCH*NPIX; t += NLB*256) {
        const float* q  = g_Qa    + (size_t)t*CP;
        const float* pr = g_probs + (size_t)t*CP;
        float ps[NCH];
        float s = 0.f;
        #pragma unroll
        for (int c = 0; c < NCH; c++) { ps[c] = fmaxf(q[c], EPSV); s += ps[c]; }
        float inv = 1.0f/s;
        #pragma unroll
        for (int c = 0; c < NCH; c++) {
            float p = ps[c]*inv;
            float r = p/pr[c];
            r = fminf(fmaxf(r, 0.05f), 20.0f);
            part += p*__logf(r);
        }
    }
    for (int o = 16; o; o >>= 1) part += __shfl_down_sync(0xffffffffu, part, o);
    __shared__ float red[8];
    int wid = tid >> 5, lane = tid & 31;
    if (lane == 0) red[wid] = part;
    __syncthreads();
    if (wid == 0) {
        float v = (lane < 8) ? red[lane] : 0.f;
        for (int o = 4; o; o >>= 1) v += __shfl_down_sync(0xffffffffu, v, o);
        if (lane == 0) g_lpart[blockIdx.x] = v;
    }
}

__global__ void k_loss2(float* __restrict__ out) {
    int lane = threadIdx.x;   // 64 threads
    float v = g_lpart[lane];
    for (int o = 16; o; o >>= 1) v += __shfl_down_sync(0xffffffffu, v, o);
    __shared__ float red[2];
    if ((lane & 31) == 0) red[lane >> 5] = v;
    __syncthreads();
    if (lane == 0) out[0] = (red[0] + red[1]) / (float)(NBATCH*NPIX);
}

extern "C" void kernel_launch(void* const* d_in, const int* in_sizes, int n_in,
                              void* d_out, int out_size) {
    const float* images  = (const float*)d_in[0];
    const float* predict = (const float*)d_in[1];
    if (n_in >= 2 && in_sizes[0] < in_sizes[1]) {
        const float* tmp = images; images = predict; predict = tmp;
    }

    k_rsg<<<(NPIX + 255)/256, 256>>>();
    k_resize<<<(NBATCH*NPIX + 127)/128, 128>>>(images);
    k_probs<<<(NBATCH*NPIX + 127)/128, 128>>>(predict);
    k_sums<<<dim3(NPIX, NBATCH), 256>>>();
    k_keff<<<dim3((NPIX + 255)/256, NPIX, NBATCH), 256>>>();
    for (int it = 0; it < NITERS; it++) {
        int dir = it & 1;
        k_msg<<<dim3((NPIX + TILE_M - 1)/TILE_M, KSPLIT, NBATCH), 128>>>(dir);
        k_update<<<(NBATCH*NPIX + 127)/128, 128>>>(dir);
    }
    k_loss1<<<NLB, 256>>>();
    k_loss2<<<1, 64>>>((float*)d_out);
}

// round 10
// speedup vs baseline: 4.0383x; 2.0818x over previous
#include <cuda_runtime.h>
#include <cuda_bf16.h>
#include <math.h>
#include <stdint.h>

#define H_IN 321
#define W_IN 321
#define WS 41
#define NPIX 1681
#define NCH 21
#define CP 24
#define NBATCH 16
#define NITERS 10

#define INVSC (321.0f/41.0f)
#define AG 8.0f                 /* 1/(2*(3/12)^2) */
#define ABF 0.011250f           /* 1/(2*(80/12)^2) */
#define BBF (1.0f/338.0f)       /* 1/(2*13^2) */
#define CG 3.0f
#define CB 10.0f
#define EPSV 1e-5f

#define KPAD 1728               /* 27*64: padded k extent of K and Qcm */
#define MPAD 1792               /* 14*128: padded row extent of K */
#define NCHUNK 27
#define TI 16                   /* keff i-tile */
#define NLB 64
#define ASTR 72                 /* padded smem row stride (bf16 elems), 72*2=144B */

__device__ __forceinline__ int div41(int j) { return (j*51151) >> 21; }

// ---------------- static device buffers ----------------
static __device__ float  g_colors[NBATCH*NPIX*4];
static __device__ float2 g_pos[NPIX];
static __device__ float  g_rsg[NPIX];
static __device__ float  g_rsb[NBATCH*NPIX];
static __device__ float  g_probs[NBATCH*NPIX*CP];
static __device__ float  g_logu[NBATCH*NPIX*CP];
static __device__ float  g_Qa[NBATCH*NPIX*CP];            // row-major fp32 Q (for loss)
static __device__ float  g_lpart[NLB];
static __device__ unsigned short g_Kh[(size_t)NBATCH*MPAD*KPAD];      // bf16 Keff, zero-padded
static __device__ unsigned short g_Qcm[(size_t)2*NBATCH*32*KPAD];     // bf16 Q channel-major x2

__device__ __forceinline__ uint32_t s2u(const void* p) {
    uint32_t a;
    asm("{ .reg .u64 t; cvta.to.shared.u64 t, %1; cvt.u32.u64 %0, t; }" : "=r"(a) : "l"(p));
    return a;
}

// ---------------- setup ----------------

__global__ void k_rsg() {
    int i = blockIdx.x*blockDim.x + threadIdx.x;
    if (i >= NPIX) return;
    int y = div41(i), x = i - y*41;
    g_pos[i] = make_float2((float)x, (float)y);
    float Sx = 0.f, Sy = 0.f;
    for (int j = 0; j < WS; j++) {
        int dx = x - j; Sx += expf(-AG * (float)(dx*dx));
        int dy = y - j; Sy += expf(-AG * (float)(dy*dy));
    }
    g_rsg[i] = rsqrtf(Sx*Sy - 1.0f);
}

__global__ void k_resize(const float* __restrict__ img) {
    int t = blockIdx.x*blockDim.x + threadIdx.x;
    if (t >= NBATCH*NPIX) return;
    int n = t / NPIX, p = t - n*NPIX;
    int oy = div41(p), ox = p - oy*41;

    float wy[18], wx[18];
    float sy = (oy + 0.5f)*INVSC - 0.5f;
    int jy0 = max(0, (int)ceilf(sy - INVSC));
    int jy1 = min(H_IN-1, (int)floorf(sy + INVSC));
    float sumy = 0.f;
    for (int j = jy0; j <= jy1; j++) {
        float w = fmaxf(1.0f - fabsf(sy - (float)j)*(1.0f/INVSC), 0.f);
        wy[j-jy0] = w; sumy += w;
    }
    float sx = (ox + 0.5f)*INVSC - 0.5f;
    int jx0 = max(0, (int)ceilf(sx - INVSC));
    int jx1 = min(W_IN-1, (int)floorf(sx + INVSC));
    float sumx = 0.f;
    for (int j = jx0; j <= jx1; j++) {
        float w = fmaxf(1.0f - fabsf(sx - (float)j)*(1.0f/INVSC), 0.f);
        wx[j-jx0] = w; sumx += w;
    }

    float a0 = 0.f, a1 = 0.f, a2 = 0.f;
    const float* b0 = img + (size_t)(n*3 + 0)*H_IN*W_IN;
    const float* b1 = img + (size_t)(n*3 + 1)*H_IN*W_IN;
    const float* b2 = img + (size_t)(n*3 + 2)*H_IN*W_IN;
    for (int jy = jy0; jy <= jy1; jy++) {
        float wyv = wy[jy-jy0];
        const float* r0 = b0 + (size_t)jy*W_IN;
        const float* r1 = b1 + (size_t)jy*W_IN;
        const float* r2 = b2 + (size_t)jy*W_IN;
        for (int jx = jx0; jx <= jx1; jx++) {
            float w = wyv * wx[jx-jx0];
            a0 = fmaf(w, r0[jx], a0);
            a1 = fmaf(w, r1[jx], a1);
            a2 = fmaf(w, r2[jx], a2);
        }
    }
    float inv = 1.0f/(sumy*sumx);
    float4 c; c.x = a0*inv; c.y = a1*inv; c.z = a2*inv; c.w = 0.f;
    ((float4*)g_colors)[t] = c;
}

// zero both Qcm buffers (pads stay zero through the run)
__global__ void k_qzero() {
    size_t t = (size_t)blockIdx.x*256 + threadIdx.x;
    size_t tot = (size_t)2*NBATCH*32*KPAD/8;
    if (t < tot) ((uint4*)g_Qcm)[t] = make_uint4(0,0,0,0);
}

__global__ void k_probs(const float* __restrict__ pred) {
    int t = blockIdx.x*blockDim.x + threadIdx.x;
    if (t >= NBATCH*NPIX) return;
    int n = t / NPIX, p = t - n*NPIX;
    const float* base = pred + (size_t)n*NCH*NPIX + p;
    float x[NCH];
    float m = -1e30f;
    #pragma unroll
    for (int c = 0; c < NCH; c++) { x[c] = base[(size_t)c*NPIX]; m = fmaxf(m, x[c]); }
    float s = 0.f;
    #pragma unroll
    for (int c = 0; c < NCH; c++) { x[c] = __expf(x[c]-m); s += x[c]; }
    float inv = 1.0f/s;
    float s2 = 0.f;
    #pragma unroll
    for (int c = 0; c < NCH; c++) { x[c] = fminf(fmaxf(x[c]*inv, EPSV), 1.0f); s2 += x[c]; }
    float inv2 = 1.0f/s2;
    float* pp = g_probs + (size_t)t*CP;
    float* pl = g_logu  + (size_t)t*CP;
    unsigned short* qc = g_Qcm + (size_t)n*32*KPAD;   // buffer 0
    #pragma unroll
    for (int c = 0; c < NCH; c++) {
        float v = x[c]*inv2;
        pp[c] = v; pl[c] = __logf(v);
        unsigned int b;
        asm("cvt.rn.bf16x2.f32 %0, %1, %2;" : "=r"(b) : "f"(0.f), "f"(v));
        qc[(size_t)c*KPAD + p] = (unsigned short)(b & 0xffffu);
    }
    #pragma unroll
    for (int c = NCH; c < CP; c++) { pp[c] = 0.f; pl[c] = 0.f; }
}

// bilateral row sums (R8 exact)
__global__ void k_sums() {
    int i = blockIdx.x, n = blockIdx.y;
    int tid = threadIdx.x;
    const float4* cols = ((const float4*)g_colors) + (size_t)n*NPIX;
    float4 ci = cols[i];
    float2 pi = g_pos[i];
    float sum = 0.f;
    for (int j = tid; j < NPIX; j += 256) {
        float2 pj = g_pos[j];
        float4 cj = cols[j];
        float dy = pi.y - pj.y, dx = pi.x - pj.x;
        float dr = ci.x - cj.x, dg = ci.y - cj.y, db = ci.z - cj.z;
        float d2 = fmaf(dy, dy, dx*dx);
        float cd2 = fmaf(dr, dr, fmaf(dg, dg, db*db));
        sum += __expf(fmaf(-ABF, d2, -BBF*cd2));
    }
    for (int o = 16; o; o >>= 1) sum += __shfl_down_sync(0xffffffffu, sum, o);
    __shared__ float red[8];
    int wid = tid >> 5, lane = tid & 31;
    if (lane == 0) red[wid] = sum;
    __syncthreads();
    if (wid == 0) {
        float v = (lane < 8) ? red[lane] : 0.f;
        for (int o = 4; o; o >>= 1) v += __shfl_down_sync(0xffffffffu, v, o);
        if (lane == 0) g_rsb[n*NPIX + i] = rsqrtf(v - 1.0f);
    }
}

// Keff = 10*Kb_norm + 3*Kg_norm, diag 0; bf16; i-tiled x16; zero-pads rows/cols
__global__ void __launch_bounds__(256) k_keff() {
    __shared__ float4 Ci[TI];
    __shared__ float2 Pi[TI];
    __shared__ float  Rb[TI], Rg[TI];
    int n = blockIdx.z;
    int i0 = blockIdx.y*TI;
    int jp = blockIdx.x*256 + threadIdx.x;   // pair index
    const float4* cols = ((const float4*)g_colors) + (size_t)n*NPIX;
    if (threadIdx.x < TI) {
        int ii = min(i0 + threadIdx.x, NPIX-1);
        Ci[threadIdx.x] = cols[ii];
        Pi[threadIdx.x] = g_pos[ii];
        Rb[threadIdx.x] = g_rsb[n*NPIX + ii];
        Rg[threadIdx.x] = g_rsg[ii];
    }
    __syncthreads();
    if (jp >= KPAD/2) return;
    int j0 = 2*jp, j1 = j0 + 1;
    int j0c = min(j0, NPIX-1), j1c = min(j1, NPIX-1);
    float4 cA = cols[j0c], cB = cols[j1c];
    float2 pA = g_pos[j0c], pB = g_pos[j1c];
    float rbA = g_rsb[n*NPIX+j0c], rbB = g_rsb[n*NPIX+j1c];
    float rgA = g_rsg[j0c], rgB = g_rsg[j1c];
    unsigned int* out = (unsigned int*)(g_Kh + ((size_t)n*MPAD + i0)*KPAD) + jp;
    #pragma unroll 4
    for (int ii = 0; ii < TI; ii++) {
        int i = i0 + ii;
        float4 ci = Ci[ii]; float2 pi = Pi[ii];
        float rbi = Rb[ii], rgi = Rg[ii];
        float v0 = 0.f, v1 = 0.f;
        if (i < NPIX) {
            {
                float dy = pi.y - pA.y, dx = pi.x - pA.x;
                float dr = ci.x - cA.x, dg = ci.y - cA.y, db = ci.z - cA.z;
                float d2 = fmaf(dy, dy, dx*dx);
                float cd2 = fmaf(dr, dr, fmaf(dg, dg, db*db));
                float kb = __expf(fmaf(-ABF, d2, -BBF*cd2)) * rbi * rbA;
                float kg = __expf(-AG * d2) * rgi * rgA;
                v0 = fmaf(CB, kb, CG*kg);
                if (j0 >= NPIX || j0 == i) v0 = 0.f;
            }
            {
                float dy = pi.y - pB.y, dx = pi.x - pB.x;
                float dr = ci.x - cB.x, dg = ci.y - cB.y, db = ci.z - cB.z;
                float d2 = fmaf(dy, dy, dx*dx);
                float cd2 = fmaf(dr, dr, fmaf(dg, dg, db*db));
                float kb = __expf(fmaf(-ABF, d2, -BBF*cd2)) * rbi * rbB;
                float kg = __expf(-AG * d2) * rgi * rgB;
                v1 = fmaf(CB, kb, CG*kg);
                if (j1 >= NPIX || j1 == i) v1 = 0.f;
            }
        }
        unsigned int pk;
        asm("cvt.rn.bf16x2.f32 %0, %1, %2;" : "=r"(pk) : "f"(v1), "f"(v0));
        out[(size_t)ii*(KPAD/2)] = pk;
    }
}

// ---------------- fused msg GEMM (mma.sync bf16) + softmax update ----------------
// block: 256 thr = 8 warps; tile 128 rows x 24 ch; warp = 16 rows.
// D = K[128 x 1728] @ Qcm^T (Qcm is channel-major = col-major B), k-chunks of 64,
// double-buffered smem + register prefetch. Epilogue: quad-shfl softmax with logu.
__global__ void __launch_bounds__(256) k_mma(int dir) {
    __shared__ unsigned short As[2][128*ASTR];
    __shared__ unsigned short Bs[2][24*ASTR];
    int tid = threadIdx.x;
    int lane = tid & 31, w = tid >> 5;
    int n = blockIdx.y, m0 = blockIdx.x*128;
    const unsigned short* Kn = g_Kh + ((size_t)n*MPAD + m0)*KPAD;
    const unsigned short* Qc = g_Qcm + ((size_t)dir*NBATCH + n)*32*KPAD;
    unsigned short*       Qo = g_Qcm + ((size_t)(dir^1)*NBATCH + n)*32*KPAD;

    float acc[3][4];
    #pragma unroll
    for (int g = 0; g < 3; g++)
        #pragma unroll
        for (int i = 0; i < 4; i++) acc[g][i] = 0.f;

    // prologue: stage chunk 0 into buffer 0
    #pragma unroll
    for (int r = 0; r < 4; r++) {
        int u = tid + 256*r, row = u >> 3, g = u & 7;
        *(uint4*)&As[0][row*ASTR + g*8] = *(const uint4*)(Kn + (size_t)row*KPAD + g*8);
    }
    if (tid < 192) {
        int c = tid >> 3, g = tid & 7;
        *(uint4*)&Bs[0][c*ASTR + g*8] = *(const uint4*)(Qc + (size_t)c*KPAD + g*8);
    }
    __syncthreads();

    uint32_t asBase = s2u(As), bsBase = s2u(Bs);

    for (int ch = 0; ch < NCHUNK; ch++) {
        int cur = ch & 1, nxt = cur ^ 1;
        uint4 aR[4]; uint4 bR;
        bool pf = (ch + 1 < NCHUNK);
        if (pf) {
            #pragma unroll
            for (int r = 0; r < 4; r++) {
                int u = tid + 256*r, row = u >> 3, g = u & 7;
                aR[r] = *(const uint4*)(Kn + (size_t)row*KPAD + (ch+1)*64 + g*8);
            }
            if (tid < 192) {
                int c = tid >> 3, g = tid & 7;
                bR = *(const uint4*)(Qc + (size_t)c*KPAD + (ch+1)*64 + g*8);
            }
        }
        uint32_t Ab = asBase + (uint32_t)(cur*128*ASTR*2);
        uint32_t Bb = bsBase + (uint32_t)(cur*24*ASTR*2);
        #pragma unroll
        for (int kk = 0; kk < 4; kk++) {
            uint32_t a0,a1,a2,a3;
            uint32_t aaddr = Ab + (uint32_t)(((w*16 + (lane & 15))*ASTR + kk*16 + (lane >> 4)*8)*2);
            asm volatile("ldmatrix.sync.aligned.m8n8.x4.shared.b16 {%0,%1,%2,%3}, [%4];"
                         : "=r"(a0),"=r"(a1),"=r"(a2),"=r"(a3) : "r"(aaddr));
            #pragma unroll
            for (int g = 0; g < 3; g++) {
                uint32_t b0,b1;
                uint32_t baddr = Bb + (uint32_t)((((g*8 + (lane>>2)))*ASTR + kk*16 + (lane&3)*2)*2);
                asm volatile("ld.shared.b32 %0, [%1];" : "=r"(b0) : "r"(baddr));
                asm volatile("ld.shared.b32 %0, [%1];" : "=r"(b1) : "r"(baddr + 16));
                asm volatile("mma.sync.aligned.m16n8k16.row.col.f32.bf16.bf16.f32 "
                             "{%0,%1,%2,%3}, {%4,%5,%6,%7}, {%8,%9}, {%0,%1,%2,%3};"
                             : "+f"(acc[g][0]),"+f"(acc[g][1]),"+f"(acc[g][2]),"+f"(acc[g][3])
                             : "r"(a0),"r"(a1),"r"(a2),"r"(a3), "r"(b0),"r"(b1));
            }
        }
        if (pf) {
            #pragma unroll
            for (int r = 0; r < 4; r++) {
                int u = tid + 256*r, row = u >> 3, g = u & 7;
                *(uint4*)&As[nxt][row*ASTR + g*8] = aR[r];
            }
            if (tid < 192) {
                int c = tid >> 3, g = tid & 7;
                *(uint4*)&Bs[nxt][c*ASTR + g*8] = bR;
            }
        }
        __syncthreads();
    }

    // epilogue: fragment layout m16n8: acc[g][0,1]=(r_lo, c0,c0+1), acc[g][2,3]=(r_hi, ...)
    int q = lane & 3;
    int r_lo = m0 + w*16 + (lane >> 2);
    const float* lgB = g_logu + (size_t)n*NPIX*CP;
    float* qaB = g_Qa + (size_t)n*NPIX*CP;

    #pragma unroll
    for (int half = 0; half < 2; half++) {
        int row = r_lo + half*8;
        int rowc = min(row, NPIX-1);
        const float* lg = lgB + (size_t)rowc*CP;
        float lt[6];
        #pragma unroll
        for (int g = 0; g < 3; g++) {
            int c0 = 8*g + 2*q;
            float2 l2 = *(const float2*)(lg + c0);
            lt[2*g]   = (c0   < NCH) ? l2.x + acc[g][half*2]   : -1e30f;
            lt[2*g+1] = (c0+1 < NCH) ? l2.y + acc[g][half*2+1] : -1e30f;
        }
        float mx = lt[0];
        #pragma unroll
        for (int i = 1; i < 6; i++) mx = fmaxf(mx, lt[i]);
        mx = fmaxf(mx, __shfl_xor_sync(0xffffffffu, mx, 1));
        mx = fmaxf(mx, __shfl_xor_sync(0xffffffffu, mx, 2));
        float e[6], s = 0.f;
        #pragma unroll
        for (int i = 0; i < 6; i++) { e[i] = __expf(lt[i]-mx); s += e[i]; }
        s += __shfl_xor_sync(0xffffffffu, s, 1);
        s += __shfl_xor_sync(0xffffffffu, s, 2);
        float inv = 1.0f/s;
        if (row < NPIX) {
            float* o = qaB + (size_t)row*CP;
            #pragma unroll
            for (int g = 0; g < 3; g++) {
                int c0 = 8*g + 2*q;
                float p0 = e[2*g]*inv, p1 = e[2*g+1]*inv;
                *(float2*)(o + c0) = make_float2(p0, p1);
                if (c0 < NCH) {
                    unsigned int b;
                    asm("cvt.rn.bf16x2.f32 %0, %1, %2;" : "=r"(b) : "f"(p1), "f"(p0));
                    Qo[(size_t)c0*KPAD + row] = (unsigned short)(b & 0xffffu);
                    if (c0 + 1 < NCH)
                        Qo[(size_t)(c0+1)*KPAD + row] = (unsigned short)(b >> 16);
                }
            }
        }
    }
}

// ---------------- loss (R8 exact) ----------------
__global__ void k_loss1() {
    int tid = threadIdx.x;
    float part = 0.f;
    for (int t = blockIdx.x*256 + tid; t < NBATCH*NPIX; t += NLB*256) {
        const float* q  = g_Qa    + (size_t)t*CP;
        const float* pr = g_probs + (size_t)t*CP;
        float ps[NCH];
        float s = 0.f;
        #pragma unroll
        for (int c = 0; c < NCH; c++) { ps[c] = fmaxf(q[c], EPSV); s += ps[c]; }
        float inv = 1.0f/s;
        #pragma unroll
        for (int c = 0; c < NCH; c++) {
            float p = ps[c]*inv;
            float r = p/pr[c];
            r = fminf(fmaxf(r, 0.05f), 20.0f);
            part += p*__logf(r);
        }
    }
    for (int o = 16; o; o >>= 1) part += __shfl_down_sync(0xffffffffu, part, o);
    __shared__ float red[8];
    int wid = tid >> 5, lane = tid & 31;
    if (lane == 0) red[wid] = part;
    __syncthreads();
    if (wid == 0) {
        float v = (lane < 8) ? red[lane] : 0.f;
        for (int o = 4; o; o >>= 1) v += __shfl_down_sync(0xffffffffu, v, o);
        if (lane == 0) g_lpart[blockIdx.x] = v;
    }
}

__global__ void k_loss2(float* __restrict__ out) {
    int lane = threadIdx.x;   // 64 threads
    float v = g_lpart[lane];
    for (int o = 16; o; o >>= 1) v += __shfl_down_sync(0xffffffffu, v, o);
    __shared__ float red[2];
    if ((lane & 31) == 0) red[lane >> 5] = v;
    __syncthreads();
    if (lane == 0) out[0] = (red[0] + red[1]) / (float)(NBATCH*NPIX);
}

extern "C" void kernel_launch(void* const* d_in, const int* in_sizes, int n_in,
                              void* d_out, int out_size) {
    const float* images  = (const float*)d_in[0];
    const float* predict = (const float*)d_in[1];
    if (n_in >= 2 && in_sizes[0] < in_sizes[1]) {
        const float* tmp = images; images = predict; predict = tmp;
    }

    k_rsg<<<(NPIX + 255)/256, 256>>>();
    k_resize<<<(NBATCH*NPIX + 127)/128, 128>>>(images);
    k_qzero<<<(int)(((size_t)2*NBATCH*32*KPAD/8 + 255)/256), 256>>>();
    k_probs<<<(NBATCH*NPIX + 127)/128, 128>>>(predict);
    k_sums<<<dim3(NPIX, NBATCH), 256>>>();
    k_keff<<<dim3((KPAD/2 + 255)/256, MPAD/TI, NBATCH), 256>>>();
    for (int it = 0; it < NITERS; it++) {
        k_mma<<<dim3(MPAD/128, NBATCH), 256>>>(it & 1);
    }
    k_loss1<<<NLB, 256>>>();
    k_loss2<<<1, 64>>>((float*)d_out);
}

// round 12
// speedup vs baseline: 4.3061x; 1.0663x over previous
#include <cuda_runtime.h>
#include <cuda_bf16.h>
#include <math.h>
#include <stdint.h>

#define H_IN 321
#define W_IN 321
#define WS 41
#define NPIX 1681
#define NCH 21
#define CP 24
#define NBATCH 16
#define NITERS 10

#define INVSC (321.0f/41.0f)
#define AG 8.0f                 /* 1/(2*(3/12)^2) */
#define ABF 0.011250f           /* 1/(2*(80/12)^2) */
#define BBF (1.0f/338.0f)       /* 1/(2*13^2) */
#define CG 3.0f
#define CB 10.0f
#define EPSV 1e-5f

#define KPAD 1728               /* 27*64: padded k extent of K and Qcm */
#define MPAD 1792               /* 14*128: padded row extent of K */
#define NCHUNK 27
#define TI 16                   /* keff i-tile */
#define NLB 64
#define ASTR 72                 /* padded smem row stride (bf16 elems), 72*2=144B */

__device__ __forceinline__ int div41(int j) { return (j*51151) >> 21; }

// ---------------- static device buffers ----------------
static __device__ float  g_colors[NBATCH*NPIX*4];
static __device__ float2 g_pos[NPIX];
static __device__ float  g_rsg[NPIX];
static __device__ float  g_rsb[NBATCH*NPIX];
static __device__ float  g_probs[NBATCH*NPIX*CP];
static __device__ float  g_logu[NBATCH*NPIX*CP];
static __device__ float  g_Qa[NBATCH*NPIX*CP];            // row-major fp32 Q (for loss)
static __device__ float  g_lpart[NLB];
static __device__ unsigned short g_Kh[(size_t)NBATCH*MPAD*KPAD];      // bf16 Keff, zero-padded
static __device__ unsigned short g_Qcm[(size_t)2*NBATCH*32*KPAD];     // bf16 Q channel-major x2

__device__ __forceinline__ uint32_t s2u(const void* p) {
    uint32_t a;
    asm("{ .reg .u64 t; cvta.to.shared.u64 t, %1; cvt.u32.u64 %0, t; }" : "=r"(a) : "l"(p));
    return a;
}
struct U32B { uint4 lo, hi; };
// 32B K load with L2 evict_last (v4.b64 is the shape ptxas accepts with the hint):
// keeps the 99MB K array resident in the 126MB L2 across the 10 iterations.
__device__ __forceinline__ U32B ldg_el32(const unsigned short* p) {
    unsigned long long a, b, c, d;
    asm volatile("ld.global.nc.L2::evict_last.v4.b64 {%0,%1,%2,%3}, [%4];"
                 : "=l"(a), "=l"(b), "=l"(c), "=l"(d) : "l"(p));
    U32B v;
    v.lo.x = (uint32_t)a; v.lo.y = (uint32_t)(a >> 32);
    v.lo.z = (uint32_t)b; v.lo.w = (uint32_t)(b >> 32);
    v.hi.x = (uint32_t)c; v.hi.y = (uint32_t)(c >> 32);
    v.hi.z = (uint32_t)d; v.hi.w = (uint32_t)(d >> 32);
    return v;
}

// ---------------- setup ----------------

__global__ void k_rsg() {
    int i = blockIdx.x*blockDim.x + threadIdx.x;
    if (i >= NPIX) return;
    int y = div41(i), x = i - y*41;
    g_pos[i] = make_float2((float)x, (float)y);
    float Sx = 0.f, Sy = 0.f;
    for (int j = 0; j < WS; j++) {
        int dx = x - j; Sx += expf(-AG * (float)(dx*dx));
        int dy = y - j; Sy += expf(-AG * (float)(dy*dy));
    }
    g_rsg[i] = rsqrtf(Sx*Sy - 1.0f);
}

__global__ void k_resize(const float* __restrict__ img) {
    int t = blockIdx.x*blockDim.x + threadIdx.x;
    if (t >= NBATCH*NPIX) return;
    int n = t / NPIX, p = t - n*NPIX;
    int oy = div41(p), ox = p - oy*41;

    float wy[18], wx[18];
    float sy = (oy + 0.5f)*INVSC - 0.5f;
    int jy0 = max(0, (int)ceilf(sy - INVSC));
    int jy1 = min(H_IN-1, (int)floorf(sy + INVSC));
    float sumy = 0.f;
    for (int j = jy0; j <= jy1; j++) {
        float w = fmaxf(1.0f - fabsf(sy - (float)j)*(1.0f/INVSC), 0.f);
        wy[j-jy0] = w; sumy += w;
    }
    float sx = (ox + 0.5f)*INVSC - 0.5f;
    int jx0 = max(0, (int)ceilf(sx - INVSC));
    int jx1 = min(W_IN-1, (int)floorf(sx + INVSC));
    float sumx = 0.f;
    for (int j = jx0; j <= jx1; j++) {
        float w = fmaxf(1.0f - fabsf(sx - (float)j)*(1.0f/INVSC), 0.f);
        wx[j-jx0] = w; sumx += w;
    }

    float a0 = 0.f, a1 = 0.f, a2 = 0.f;
    const float* b0 = img + (size_t)(n*3 + 0)*H_IN*W_IN;
    const float* b1 = img + (size_t)(n*3 + 1)*H_IN*W_IN;
    const float* b2 = img + (size_t)(n*3 + 2)*H_IN*W_IN;
    for (int jy = jy0; jy <= jy1; jy++) {
        float wyv = wy[jy-jy0];
        const float* r0 = b0 + (size_t)jy*W_IN;
        const float* r1 = b1 + (size_t)jy*W_IN;
        const float* r2 = b2 + (size_t)jy*W_IN;
        for (int jx = jx0; jx <= jx1; jx++) {
            float w = wyv * wx[jx-jx0];
            a0 = fmaf(w, r0[jx], a0);
            a1 = fmaf(w, r1[jx], a1);
            a2 = fmaf(w, r2[jx], a2);
        }
    }
    float inv = 1.0f/(sumy*sumx);
    float4 c; c.x = a0*inv; c.y = a1*inv; c.z = a2*inv; c.w = 0.f;
    ((float4*)g_colors)[t] = c;
}

// zero both Qcm buffers (pads stay zero through the run)
__global__ void k_qzero() {
    size_t t = (size_t)blockIdx.x*256 + threadIdx.x;
    size_t tot = (size_t)2*NBATCH*32*KPAD/8;
    if (t < tot) ((uint4*)g_Qcm)[t] = make_uint4(0,0,0,0);
}

__global__ void k_probs(const float* __restrict__ pred) {
    int t = blockIdx.x*blockDim.x + threadIdx.x;
    if (t >= NBATCH*NPIX) return;
    int n = t / NPIX, p = t - n*NPIX;
    const float* base = pred + (size_t)n*NCH*NPIX + p;
    float x[NCH];
    float m = -1e30f;
    #pragma unroll
    for (int c = 0; c < NCH; c++) { x[c] = base[(size_t)c*NPIX]; m = fmaxf(m, x[c]); }
    float s = 0.f;
    #pragma unroll
    for (int c = 0; c < NCH; c++) { x[c] = __expf(x[c]-m); s += x[c]; }
    float inv = 1.0f/s;
    float s2 = 0.f;
    #pragma unroll
    for (int c = 0; c < NCH; c++) { x[c] = fminf(fmaxf(x[c]*inv, EPSV), 1.0f); s2 += x[c]; }
    float inv2 = 1.0f/s2;
    float* pp = g_probs + (size_t)t*CP;
    float* pl = g_logu  + (size_t)t*CP;
    unsigned short* qc = g_Qcm + (size_t)n*32*KPAD;   // buffer 0
    #pragma unroll
    for (int c = 0; c < NCH; c++) {
        float v = x[c]*inv2;
        pp[c] = v; pl[c] = __logf(v);
        unsigned int b;
        asm("cvt.rn.bf16x2.f32 %0, %1, %2;" : "=r"(b) : "f"(0.f), "f"(v));
        qc[(size_t)c*KPAD + p] = (unsigned short)(b & 0xffffu);
    }
    #pragma unroll
    for (int c = NCH; c < CP; c++) { pp[c] = 0.f; pl[c] = 0.f; }
}

// bilateral row sums, i-tiled x4: 4 consecutive i's share every j-feature load
__global__ void __launch_bounds__(256) k_sums() {
    int n = blockIdx.y;
    int i0 = blockIdx.x*4;
    int tid = threadIdx.x;
    const float4* cols = ((const float4*)g_colors) + (size_t)n*NPIX;
    float4 ci[4]; float2 pi[4];
    #pragma unroll
    for (int ii = 0; ii < 4; ii++) {
        int i = min(i0 + ii, NPIX-1);
        ci[ii] = cols[i]; pi[ii] = g_pos[i];
    }
    float sum[4] = {0.f, 0.f, 0.f, 0.f};
    for (int j = tid; j < NPIX; j += 256) {
        float2 pj = g_pos[j];
        float4 cj = cols[j];
        #pragma unroll
        for (int ii = 0; ii < 4; ii++) {
            float dy = pi[ii].y - pj.y, dx = pi[ii].x - pj.x;
            float dr = ci[ii].x - cj.x, dg = ci[ii].y - cj.y, db = ci[ii].z - cj.z;
            float d2 = fmaf(dy, dy, dx*dx);
            float cd2 = fmaf(dr, dr, fmaf(dg, dg, db*db));
            sum[ii] += __expf(fmaf(-ABF, d2, -BBF*cd2));
        }
    }
    __shared__ float red[4][8];
    int wid = tid >> 5, lane = tid & 31;
    #pragma unroll
    for (int ii = 0; ii < 4; ii++) {
        float v = sum[ii];
        for (int o = 16; o; o >>= 1) v += __shfl_down_sync(0xffffffffu, v, o);
        if (lane == 0) red[ii][wid] = v;
    }
    __syncthreads();
    if (tid < 4) {
        float v = 0.f;
        #pragma unroll
        for (int w = 0; w < 8; w++) v += red[tid][w];
        int i = i0 + tid;
        if (i < NPIX) g_rsb[n*NPIX + i] = rsqrtf(v - 1.0f);  // self term exp(0)=1
    }
}

// Keff = 10*Kb_norm + 3*Kg_norm, diag 0; bf16; i-tiled x16; kg gated (exp(-8*12.5)=0)
__global__ void __launch_bounds__(256) k_keff() {
    __shared__ float4 Ci[TI];
    __shared__ float2 Pi[TI];
    __shared__ float  Rb[TI], Rg[TI];
    int n = blockIdx.z;
    int i0 = blockIdx.y*TI;
    int jp = blockIdx.x*256 + threadIdx.x;   // pair index
    const float4* cols = ((const float4*)g_colors) + (size_t)n*NPIX;
    if (threadIdx.x < TI) {
        int ii = min(i0 + threadIdx.x, NPIX-1);
        Ci[threadIdx.x] = cols[ii];
        Pi[threadIdx.x] = g_pos[ii];
        Rb[threadIdx.x] = g_rsb[n*NPIX + ii];
        Rg[threadIdx.x] = g_rsg[ii];
    }
    __syncthreads();
    if (jp >= KPAD/2) return;
    int j0 = 2*jp, j1 = j0 + 1;
    int j0c = min(j0, NPIX-1), j1c = min(j1, NPIX-1);
    float4 cA = cols[j0c], cB = cols[j1c];
    float2 pA = g_pos[j0c], pB = g_pos[j1c];
    float rbA = g_rsb[n*NPIX+j0c], rbB = g_rsb[n*NPIX+j1c];
    float rgA = g_rsg[j0c], rgB = g_rsg[j1c];
    unsigned int* out = (unsigned int*)(g_Kh + ((size_t)n*MPAD + i0)*KPAD) + jp;
    #pragma unroll 4
    for (int ii = 0; ii < TI; ii++) {
        int i = i0 + ii;
        float4 ci = Ci[ii]; float2 pi = Pi[ii];
        float rbi = Rb[ii], rgi = Rg[ii];
        float v0 = 0.f, v1 = 0.f;
        if (i < NPIX) {
            {
                float dy = pi.y - pA.y, dx = pi.x - pA.x;
                float dr = ci.x - cA.x, dg = ci.y - cA.y, db = ci.z - cA.z;
                float d2 = fmaf(dy, dy, dx*dx);
                float cd2 = fmaf(dr, dr, fmaf(dg, dg, db*db));
                v0 = CB * __expf(fmaf(-ABF, d2, -BBF*cd2)) * rbi * rbA;
                if (d2 < 12.5f) v0 = fmaf(CG, __expf(-AG*d2)*rgi*rgA, v0);
                if (j0 >= NPIX || j0 == i) v0 = 0.f;
            }
            {
                float dy = pi.y - pB.y, dx = pi.x - pB.x;
                float dr = ci.x - cB.x, dg = ci.y - cB.y, db = ci.z - cB.z;
                float d2 = fmaf(dy, dy, dx*dx);
                float cd2 = fmaf(dr, dr, fmaf(dg, dg, db*db));
                v1 = CB * __expf(fmaf(-ABF, d2, -BBF*cd2)) * rbi * rbB;
                if (d2 < 12.5f) v1 = fmaf(CG, __expf(-AG*d2)*rgi*rgB, v1);
                if (j1 >= NPIX || j1 == i) v1 = 0.f;
            }
        }
        unsigned int pk;
        asm("cvt.rn.bf16x2.f32 %0, %1, %2;" : "=r"(pk) : "f"(v1), "f"(v0));
        out[(size_t)ii*(KPAD/2)] = pk;
    }
}

// ---------------- fused msg GEMM (mma.sync bf16) + softmax update ----------------
// block: 256 thr = 8 warps; tile 128 rows x 24 ch; warp = 16 rows.
// D = K[128 x 1728] @ Qcm^T, k-chunks of 64, double-buffered smem + reg prefetch.
// K loads: 32B ld.global.nc.L2::evict_last.v4.b64 (99MB K stays L2-resident).
__global__ void __launch_bounds__(256) k_mma(int dir) {
    __shared__ unsigned short As[2][128*ASTR];
    __shared__ unsigned short Bs[2][24*ASTR];
    int tid = threadIdx.x;
    int lane = tid & 31, w = tid >> 5;
    int n = blockIdx.y, m0 = blockIdx.x*128;
    const unsigned short* Kn = g_Kh + ((size_t)n*MPAD + m0)*KPAD;
    const unsigned short* Qc = g_Qcm + ((size_t)dir*NBATCH + n)*32*KPAD;
    unsigned short*       Qo = g_Qcm + ((size_t)(dir^1)*NBATCH + n)*32*KPAD;

    float acc[3][4];
    #pragma unroll
    for (int g = 0; g < 3; g++)
        #pragma unroll
        for (int i = 0; i < 4; i++) acc[g][i] = 0.f;

    // prologue: stage chunk 0 into buffer 0 (A: 512 x 32B loads, 2/thread)
    #pragma unroll
    for (int r = 0; r < 2; r++) {
        int u = tid + 256*r, row = u >> 2, g = u & 3;   // row 0..127, g = 32B group
        U32B v = ldg_el32(Kn + (size_t)row*KPAD + g*16);
        *(uint4*)&As[0][row*ASTR + g*16]     = v.lo;
        *(uint4*)&As[0][row*ASTR + g*16 + 8] = v.hi;
    }
    if (tid < 192) {
        int c = tid >> 3, g = tid & 7;
        *(uint4*)&Bs[0][c*ASTR + g*8] = *(const uint4*)(Qc + (size_t)c*KPAD + g*8);
    }
    __syncthreads();

    uint32_t asBase = s2u(As), bsBase = s2u(Bs);

    for (int ch = 0; ch < NCHUNK; ch++) {
        int cur = ch & 1, nxt = cur ^ 1;
        U32B aR[2]; uint4 bR;
        bool pf = (ch + 1 < NCHUNK);
        if (pf) {
            #pragma unroll
            for (int r = 0; r < 2; r++) {
                int u = tid + 256*r, row = u >> 2, g = u & 3;
                aR[r] = ldg_el32(Kn + (size_t)row*KPAD + (ch+1)*64 + g*16);
            }
            if (tid < 192) {
                int c = tid >> 3, g = tid & 7;
                bR = *(const uint4*)(Qc + (size_t)c*KPAD + (ch+1)*64 + g*8);
            }
        }
        uint32_t Ab = asBase + (uint32_t)(cur*128*ASTR*2);
        uint32_t Bb = bsBase + (uint32_t)(cur*24*ASTR*2);
        #pragma unroll
        for (int kk = 0; kk < 4; kk++) {
            uint32_t a0,a1,a2,a3;
            uint32_t aaddr = Ab + (uint32_t)(((w*16 + (lane & 15))*ASTR + kk*16 + (lane >> 4)*8)*2);
            asm volatile("ldmatrix.sync.aligned.m8n8.x4.shared.b16 {%0,%1,%2,%3}, [%4];"
                         : "=r"(a0),"=r"(a1),"=r"(a2),"=r"(a3) : "r"(aaddr));
            #pragma unroll
            for (int g = 0; g < 3; g++) {
                uint32_t b0,b1;
                uint32_t baddr = Bb + (uint32_t)((((g*8 + (lane>>2)))*ASTR + kk*16 + (lane&3)*2)*2);
                asm volatile("ld.shared.b32 %0, [%1];" : "=r"(b0) : "r"(baddr));
                asm volatile("ld.shared.b32 %0, [%1];" : "=r"(b1) : "r"(baddr + 16));
                asm volatile("mma.sync.aligned.m16n8k16.row.col.f32.bf16.bf16.f32 "
                             "{%0,%1,%2,%3}, {%4,%5,%6,%7}, {%8,%9}, {%0,%1,%2,%3};"
                             : "+f"(acc[g][0]),"+f"(acc[g][1]),"+f"(acc[g][2]),"+f"(acc[g][3])
                             : "r"(a0),"r"(a1),"r"(a2),"r"(a3), "r"(b0),"r"(b1));
            }
        }
        if (pf) {
            #pragma unroll
            for (int r = 0; r < 2; r++) {
                int u = tid + 256*r, row = u >> 2, g = u & 3;
                *(uint4*)&As[nxt][row*ASTR + g*16]     = aR[r].lo;
                *(uint4*)&As[nxt][row*ASTR + g*16 + 8] = aR[r].hi;
            }
            if (tid < 192) {
                int c = tid >> 3, g = tid & 7;
                *(uint4*)&Bs[nxt][c*ASTR + g*8] = bR;
            }
        }
        __syncthreads();
    }

    // epilogue: fragment layout m16n8: acc[g][0,1]=(r_lo, c0,c0+1), acc[g][2,3]=(r_hi, ...)
    int q = lane & 3;
    int r_lo = m0 + w*16 + (lane >> 2);
    const float* lgB = g_logu + (size_t)n*NPIX*CP;
    float* qaB = g_Qa + (size_t)n*NPIX*CP;

    #pragma unroll
    for (int half = 0; half < 2; half++) {
        int row = r_lo + half*8;
        int rowc = min(row, NPIX-1);
        const float* lg = lgB + (size_t)rowc*CP;
        float lt[6];
        #pragma unroll
        for (int g = 0; g < 3; g++) {
            int c0 = 8*g + 2*q;
            float2 l2 = *(const float2*)(lg + c0);
            lt[2*g]   = (c0   < NCH) ? l2.x + acc[g][half*2]   : -1e30f;
            lt[2*g+1] = (c0+1 < NCH) ? l2.y + acc[g][half*2+1] : -1e30f;
        }
        float mx = lt[0];
        #pragma unroll
        for (int i = 1; i < 6; i++) mx = fmaxf(mx, lt[i]);
        mx = fmaxf(mx, __shfl_xor_sync(0xffffffffu, mx, 1));
        mx = fmaxf(mx, __shfl_xor_sync(0xffffffffu, mx, 2));
        float e[6], s = 0.f;
        #pragma unroll
        for (int i = 0; i < 6; i++) { e[i] = __expf(lt[i]-mx); s += e[i]; }
        s += __shfl_xor_sync(0xffffffffu, s, 1);
        s += __shfl_xor_sync(0xffffffffu, s, 2);
        float inv = 1.0f/s;
        if (row < NPIX) {
            float* o = qaB + (size_t)row*CP;
            #pragma unroll
            for (int g = 0; g < 3; g++) {
                int c0 = 8*g + 2*q;
                float p0 = e[2*g]*inv, p1 = e[2*g+1]*inv;
                *(float2*)(o + c0) = make_float2(p0, p1);
                if (c0 < NCH) {
                    unsigned int b;
                    asm("cvt.rn.bf16x2.f32 %0, %1, %2;" : "=r"(b) : "f"(p1), "f"(p0));
                    Qo[(size_t)c0*KPAD + row] = (unsigned short)(b & 0xffffu);
                    if (c0 + 1 < NCH)
                        Qo[(size_t)(c0+1)*KPAD + row] = (unsigned short)(b >> 16);
                }
            }
        }
    }
}

// ---------------- loss ----------------
__global__ void k_loss1() {
    int tid = threadIdx.x;
    float part = 0.f;
    for (int t = blockIdx.x*256 + tid; t < NBATCH*NPIX; t += NLB*256) {
        const float* q  = g_Qa    + (size_t)t*CP;
        const float* pr = g_probs + (size_t)t*CP;
        float ps[NCH];
        float s = 0.f;
        #pragma unroll
        for (int c = 0; c < NCH; c++) { ps[c] = fmaxf(q[c], EPSV); s += ps[c]; }
        float inv = 1.0f/s;
        #pragma unroll
        for (int c = 0; c < NCH; c++) {
            float p = ps[c]*inv;
            float r = p/pr[c];
            r = fminf(fmaxf(r, 0.05f), 20.0f);
            part += p*__logf(r);
        }
    }
    for (int o = 16; o; o >>= 1) part += __shfl_down_sync(0xffffffffu, part, o);
    __shared__ float red[8];
    int wid = tid >> 5, lane = tid & 31;
    if (lane == 0) red[wid] = part;
    __syncthreads();
    if (wid == 0) {
        float v = (lane < 8) ? red[lane] : 0.f;
        for (int o = 4; o; o >>= 1) v += __shfl_down_sync(0xffffffffu, v, o);
        if (lane == 0) g_lpart[blockIdx.x] = v;
    }
}

__global__ void k_loss2(float* __restrict__ out) {
    int lane = threadIdx.x;   // 64 threads
    float v = g_lpart[lane];
    for (int o = 16; o; o >>= 1) v += __shfl_down_sync(0xffffffffu, v, o);
    __shared__ float red[2];
    if ((lane & 31) == 0) red[lane >> 5] = v;
    __syncthreads();
    if (lane == 0) out[0] = (red[0] + red[1]) / (float)(NBATCH*NPIX);
}

extern "C" void kernel_launch(void* const* d_in, const int* in_sizes, int n_in,
                              void* d_out, int out_size) {
    const float* images  = (const float*)d_in[0];
    const float* predict = (const float*)d_in[1];
    if (n_in >= 2 && in_sizes[0] < in_sizes[1]) {
        const float* tmp = images; images = predict; predict = tmp;
    }

    k_rsg<<<(NPIX + 255)/256, 256>>>();
    k_resize<<<(NBATCH*NPIX + 127)/128, 128>>>(images);
    k_qzero<<<(int)(((size_t)2*NBATCH*32*KPAD/8 + 255)/256), 256>>>();
    k_probs<<<(NBATCH*NPIX + 127)/128, 128>>>(predict);
    k_sums<<<dim3((NPIX + 3)/4, NBATCH), 256>>>();
    k_keff<<<dim3((KPAD/2 + 255)/256, MPAD/TI, NBATCH), 256>>>();
    for (int it = 0; it < NITERS; it++) {
        k_mma<<<dim3(MPAD/128, NBATCH), 256>>>(it & 1);
    }
    k_loss1<<<NLB, 256>>>();
    k_loss2<<<1, 64>>>((float*)d_out);
}

// round 14
// speedup vs baseline: 5.6532x; 1.3128x over previous
#include <cuda_runtime.h>
#include <cuda_bf16.h>
#include <math.h>
#include <stdint.h>

#define H_IN 321
#define W_IN 321
#define WS 41
#define NPIX 1681
#define NCH 21
#define CP 24
#define NBATCH 16
#define NITERS 10

#define INVSC (321.0f/41.0f)
#define AG 8.0f                 /* 1/(2*(3/12)^2) */
#define ABF 0.011250f           /* 1/(2*(80/12)^2) */
#define BBF (1.0f/338.0f)       /* 1/(2*13^2) */
#define CG 3.0f
#define CB 10.0f
#define EPSV 1e-5f

#define KPAD 1728               /* 27*64: padded k extent of K and Qcm */
#define MPAD 1792               /* 28*64: padded row extent of K */
#define NCHUNK 27
#define TI 16                   /* keff i-tile */
#define NLB 64
#define ASTR 72                 /* padded smem row stride (bf16 elems), 72*2=144B */
#define TM 64                   /* k_mma row tile */
#define NSTAGE 4

__device__ __forceinline__ int div41(int j) { return (j*51151) >> 21; }

// ---------------- static device buffers ----------------
static __device__ float  g_colors[NBATCH*NPIX*4];
static __device__ float2 g_pos[NPIX];
static __device__ float  g_rsg[NPIX];
static __device__ float  g_rsb[NBATCH*NPIX];
static __device__ float  g_probs[NBATCH*NPIX*CP];
static __device__ float  g_logu[NBATCH*NPIX*CP];
static __device__ float  g_Qa[NBATCH*NPIX*CP];            // row-major fp32 Q (for loss)
static __device__ float  g_lpart[NLB];
static __device__ unsigned short g_Kh[(size_t)NBATCH*MPAD*KPAD];      // bf16 Keff, zero-padded
static __device__ unsigned short g_Qcm[(size_t)2*NBATCH*32*KPAD];     // bf16 Q channel-major x2

__device__ __forceinline__ uint32_t s2u(const void* p) {
    uint32_t a;
    asm("{ .reg .u64 t; cvta.to.shared.u64 t, %1; cvt.u32.u64 %0, t; }" : "=r"(a) : "l"(p));
    return a;
}
__device__ __forceinline__ void cp16(uint32_t dst, const void* src) {
    asm volatile("cp.async.cg.shared.global [%0], [%1], 16;" :: "r"(dst), "l"(src));
}

// ---------------- setup ----------------

__global__ void k_rsg() {
    int i = blockIdx.x*blockDim.x + threadIdx.x;
    if (i >= NPIX) return;
    int y = div41(i), x = i - y*41;
    g_pos[i] = make_float2((float)x, (float)y);
    float Sx = 0.f, Sy = 0.f;
    for (int j = 0; j < WS; j++) {
        int dx = x - j; Sx += expf(-AG * (float)(dx*dx));
        int dy = y - j; Sy += expf(-AG * (float)(dy*dy));
    }
    g_rsg[i] = rsqrtf(Sx*Sy - 1.0f);
}

__global__ void k_resize(const float* __restrict__ img) {
    int t = blockIdx.x*blockDim.x + threadIdx.x;
    if (t >= NBATCH*NPIX) return;
    int n = t / NPIX, p = t - n*NPIX;
    int oy = div41(p), ox = p - oy*41;

    float wy[18], wx[18];
    float sy = (oy + 0.5f)*INVSC - 0.5f;
    int jy0 = max(0, (int)ceilf(sy - INVSC));
    int jy1 = min(H_IN-1, (int)floorf(sy + INVSC));
    float sumy = 0.f;
    for (int j = jy0; j <= jy1; j++) {
        float w = fmaxf(1.0f - fabsf(sy - (float)j)*(1.0f/INVSC), 0.f);
        wy[j-jy0] = w; sumy += w;
    }
    float sx = (ox + 0.5f)*INVSC - 0.5f;
    int jx0 = max(0, (int)ceilf(sx - INVSC));
    int jx1 = min(W_IN-1, (int)floorf(sx + INVSC));
    float sumx = 0.f;
    for (int j = jx0; j <= jx1; j++) {
        float w = fmaxf(1.0f - fabsf(sx - (float)j)*(1.0f/INVSC), 0.f);
        wx[j-jx0] = w; sumx += w;
    }

    float a0 = 0.f, a1 = 0.f, a2 = 0.f;
    const float* b0 = img + (size_t)(n*3 + 0)*H_IN*W_IN;
    const float* b1 = img + (size_t)(n*3 + 1)*H_IN*W_IN;
    const float* b2 = img + (size_t)(n*3 + 2)*H_IN*W_IN;
    for (int jy = jy0; jy <= jy1; jy++) {
        float wyv = wy[jy-jy0];
        const float* r0 = b0 + (size_t)jy*W_IN;
        const float* r1 = b1 + (size_t)jy*W_IN;
        const float* r2 = b2 + (size_t)jy*W_IN;
        for (int jx = jx0; jx <= jx1; jx++) {
            float w = wyv * wx[jx-jx0];
            a0 = fmaf(w, r0[jx], a0);
            a1 = fmaf(w, r1[jx], a1);
            a2 = fmaf(w, r2[jx], a2);
        }
    }
    float inv = 1.0f/(sumy*sumx);
    float4 c; c.x = a0*inv; c.y = a1*inv; c.z = a2*inv; c.w = 0.f;
    ((float4*)g_colors)[t] = c;
}

// zero both Qcm buffers (pads stay zero through the run)
__global__ void k_qzero() {
    size_t t = (size_t)blockIdx.x*256 + threadIdx.x;
    size_t tot = (size_t)2*NBATCH*32*KPAD/8;
    if (t < tot) ((uint4*)g_Qcm)[t] = make_uint4(0,0,0,0);
}

__global__ void k_probs(const float* __restrict__ pred) {
    int t = blockIdx.x*blockDim.x + threadIdx.x;
    if (t >= NBATCH*NPIX) return;
    int n = t / NPIX, p = t - n*NPIX;
    const float* base = pred + (size_t)n*NCH*NPIX + p;
    float x[NCH];
    float m = -1e30f;
    #pragma unroll
    for (int c = 0; c < NCH; c++) { x[c] = base[(size_t)c*NPIX]; m = fmaxf(m, x[c]); }
    float s = 0.f;
    #pragma unroll
    for (int c = 0; c < NCH; c++) { x[c] = __expf(x[c]-m); s += x[c]; }
    float inv = 1.0f/s;
    float s2 = 0.f;
    #pragma unroll
    for (int c = 0; c < NCH; c++) { x[c] = fminf(fmaxf(x[c]*inv, EPSV), 1.0f); s2 += x[c]; }
    float inv2 = 1.0f/s2;
    float* pp = g_probs + (size_t)t*CP;
    float* pl = g_logu  + (size_t)t*CP;
    unsigned short* qc = g_Qcm + (size_t)n*32*KPAD;   // buffer 0
    #pragma unroll
    for (int c = 0; c < NCH; c++) {
        float v = x[c]*inv2;
        pp[c] = v; pl[c] = __logf(v);
        unsigned int b;
        asm("cvt.rn.bf16x2.f32 %0, %1, %2;" : "=r"(b) : "f"(0.f), "f"(v));
        qc[(size_t)c*KPAD + p] = (unsigned short)(b & 0xffffu);
    }
    #pragma unroll
    for (int c = NCH; c < CP; c++) { pp[c] = 0.f; pl[c] = 0.f; }
}

// bilateral row sums, i-tiled x4 (R12 exact)
__global__ void __launch_bounds__(256) k_sums() {
    int n = blockIdx.y;
    int i0 = blockIdx.x*4;
    int tid = threadIdx.x;
    const float4* cols = ((const float4*)g_colors) + (size_t)n*NPIX;
    float4 ci[4]; float2 pi[4];
    #pragma unroll
    for (int ii = 0; ii < 4; ii++) {
        int i = min(i0 + ii, NPIX-1);
        ci[ii] = cols[i]; pi[ii] = g_pos[i];
    }
    float sum[4] = {0.f, 0.f, 0.f, 0.f};
    for (int j = tid; j < NPIX; j += 256) {
        float2 pj = g_pos[j];
        float4 cj = cols[j];
        #pragma unroll
        for (int ii = 0; ii < 4; ii++) {
            float dy = pi[ii].y - pj.y, dx = pi[ii].x - pj.x;
            float dr = ci[ii].x - cj.x, dg = ci[ii].y - cj.y, db = ci[ii].z - cj.z;
            float d2 = fmaf(dy, dy, dx*dx);
            float cd2 = fmaf(dr, dr, fmaf(dg, dg, db*db));
            sum[ii] += __expf(fmaf(-ABF, d2, -BBF*cd2));
        }
    }
    __shared__ float red[4][8];
    int wid = tid >> 5, lane = tid & 31;
    #pragma unroll
    for (int ii = 0; ii < 4; ii++) {
        float v = sum[ii];
        for (int o = 16; o; o >>= 1) v += __shfl_down_sync(0xffffffffu, v, o);
        if (lane == 0) red[ii][wid] = v;
    }
    __syncthreads();
    if (tid < 4) {
        float v = 0.f;
        #pragma unroll
        for (int w = 0; w < 8; w++) v += red[tid][w];
        int i = i0 + tid;
        if (i < NPIX) g_rsb[n*NPIX + i] = rsqrtf(v - 1.0f);  // self term exp(0)=1
    }
}

// Keff = 10*Kb_norm + 3*Kg_norm, diag 0; bf16; i-tiled x16; kg gated (R12 exact)
__global__ void __launch_bounds__(256) k_keff() {
    __shared__ float4 Ci[TI];
    __shared__ float2 Pi[TI];
    __shared__ float  Rb[TI], Rg[TI];
    int n = blockIdx.z;
    int i0 = blockIdx.y*TI;
    int jp = blockIdx.x*256 + threadIdx.x;   // pair index
    const float4* cols = ((const float4*)g_colors) + (size_t)n*NPIX;
    if (threadIdx.x < TI) {
        int ii = min(i0 + threadIdx.x, NPIX-1);
        Ci[threadIdx.x] = cols[ii];
        Pi[threadIdx.x] = g_pos[ii];
        Rb[threadIdx.x] = g_rsb[n*NPIX + ii];
        Rg[threadIdx.x] = g_rsg[ii];
    }
    __syncthreads();
    if (jp >= KPAD/2) return;
    int j0 = 2*jp, j1 = j0 + 1;
    int j0c = min(j0, NPIX-1), j1c = min(j1, NPIX-1);
    float4 cA = cols[j0c], cB = cols[j1c];
    float2 pA = g_pos[j0c], pB = g_pos[j1c];
    float rbA = g_rsb[n*NPIX+j0c], rbB = g_rsb[n*NPIX+j1c];
    float rgA = g_rsg[j0c], rgB = g_rsg[j1c];
    unsigned int* out = (unsigned int*)(g_Kh + ((size_t)n*MPAD + i0)*KPAD) + jp;
    #pragma unroll 4
    for (int ii = 0; ii < TI; ii++) {
        int i = i0 + ii;
        float4 ci = Ci[ii]; float2 pi = Pi[ii];
        float rbi = Rb[ii], rgi = Rg[ii];
        float v0 = 0.f, v1 = 0.f;
        if (i < NPIX) {
            {
                float dy = pi.y - pA.y, dx = pi.x - pA.x;
                float dr = ci.x - cA.x, dg = ci.y - cA.y, db = ci.z - cA.z;
                float d2 = fmaf(dy, dy, dx*dx);
                float cd2 = fmaf(dr, dr, fmaf(dg, dg, db*db));
                v0 = CB * __expf(fmaf(-ABF, d2, -BBF*cd2)) * rbi * rbA;
                if (d2 < 12.5f) v0 = fmaf(CG, __expf(-AG*d2)*rgi*rgA, v0);
                if (j0 >= NPIX || j0 == i) v0 = 0.f;
            }
            {
                float dy = pi.y - pB.y, dx = pi.x - pB.x;
                float dr = ci.x - cB.x, dg = ci.y - cB.y, db = ci.z - cB.z;
                float d2 = fmaf(dy, dy, dx*dx);
                float cd2 = fmaf(dr, dr, fmaf(dg, dg, db*db));
                v1 = CB * __expf(fmaf(-ABF, d2, -BBF*cd2)) * rbi * rbB;
                if (d2 < 12.5f) v1 = fmaf(CG, __expf(-AG*d2)*rgi*rgB, v1);
                if (j1 >= NPIX || j1 == i) v1 = 0.f;
            }
        }
        unsigned int pk;
        asm("cvt.rn.bf16x2.f32 %0, %1, %2;" : "=r"(pk) : "f"(v1), "f"(v0));
        out[(size_t)ii*(KPAD/2)] = pk;
    }
}

// ---------------- fused msg GEMM (mma.sync bf16, cp.async 4-stage) ----------------
// block: 128 thr = 4 warps; tile 64 rows x 24 ch; warp = 16 rows; grid 28x16=448.
// Pipeline: prologue stages 0..2; per iter: wait_group(2), sync, compute, issue ch+3.
__global__ void __launch_bounds__(128) k_mma(int dir) {
    extern __shared__ unsigned short sm[];
    unsigned short* As = sm;                       // NSTAGE x TM x ASTR
    unsigned short* Bs = sm + NSTAGE*TM*ASTR;      // NSTAGE x 24 x ASTR
    int tid = threadIdx.x;
    int lane = tid & 31, w = tid >> 5;
    int n = blockIdx.y, m0 = blockIdx.x*TM;
    const unsigned short* Kn = g_Kh + ((size_t)n*MPAD + m0)*KPAD;
    const unsigned short* Qc = g_Qcm + ((size_t)dir*NBATCH + n)*32*KPAD;
    unsigned short*       Qo = g_Qcm + ((size_t)(dir^1)*NBATCH + n)*32*KPAD;

    uint32_t asBase = s2u(As), bsBase = s2u(Bs);

    // issue chunk ch into stage buffer b
    auto issue = [&](int ch, int b) {
        uint32_t Ad = asBase + (uint32_t)(b*TM*ASTR*2);
        uint32_t Bd = bsBase + (uint32_t)(b*24*ASTR*2);
        const unsigned short* Ks = Kn + ch*64;
        const unsigned short* Qs = Qc + ch*64;
        #pragma unroll
        for (int r = 0; r < 4; r++) {                 // A: 64 rows x 8 x 16B = 512
            int u = tid + 128*r, row = u >> 3, g = u & 7;
            cp16(Ad + (uint32_t)((row*ASTR + g*8)*2), Ks + (size_t)row*KPAD + g*8);
        }
        {                                             // B: 24 rows x 8 x 16B = 192
            int u = tid, row = u >> 3, g = u & 7;     // threads 0..127 -> rows 0..15
            cp16(Bd + (uint32_t)((row*ASTR + g*8)*2), Qs + (size_t)row*KPAD + g*8);
            u = tid + 128;
            if (u < 192) {
                row = u >> 3; g = u & 7;
                cp16(Bd + (uint32_t)((row*ASTR + g*8)*2), Qs + (size_t)row*KPAD + g*8);
            }
        }
    };

    float acc[3][4];
    #pragma unroll
    for (int g = 0; g < 3; g++)
        #pragma unroll
        for (int i = 0; i < 4; i++) acc[g][i] = 0.f;

    // prologue: 3 stages in flight
    #pragma unroll
    for (int s = 0; s < 3; s++) {
        issue(s, s);
        asm volatile("cp.async.commit_group;" ::: "memory");
    }

    for (int ch = 0; ch < NCHUNK; ch++) {
        asm volatile("cp.async.wait_group 2;" ::: "memory");
        __syncthreads();
        int b = ch & (NSTAGE-1);
        uint32_t Ab = asBase + (uint32_t)(b*TM*ASTR*2);
        uint32_t Bb = bsBase + (uint32_t)(b*24*ASTR*2);
        #pragma unroll
        for (int kk = 0; kk < 4; kk++) {
            uint32_t a0,a1,a2,a3;
            uint32_t aaddr = Ab + (uint32_t)(((w*16 + (lane & 15))*ASTR + kk*16 + (lane >> 4)*8)*2);
            asm volatile("ldmatrix.sync.aligned.m8n8.x4.shared.b16 {%0,%1,%2,%3}, [%4];"
                         : "=r"(a0),"=r"(a1),"=r"(a2),"=r"(a3) : "r"(aaddr));
            #pragma unroll
            for (int g = 0; g < 3; g++) {
                uint32_t b0,b1;
                uint32_t baddr = Bb + (uint32_t)((((g*8 + (lane>>2)))*ASTR + kk*16 + (lane&3)*2)*2);
                asm volatile("ld.shared.b32 %0, [%1];" : "=r"(b0) : "r"(baddr));
                asm volatile("ld.shared.b32 %0, [%1];" : "=r"(b1) : "r"(baddr + 16));
                asm volatile("mma.sync.aligned.m16n8k16.row.col.f32.bf16.bf16.f32 "
                             "{%0,%1,%2,%3}, {%4,%5,%6,%7}, {%8,%9}, {%0,%1,%2,%3};"
                             : "+f"(acc[g][0]),"+f"(acc[g][1]),"+f"(acc[g][2]),"+f"(acc[g][3])
                             : "r"(a0),"r"(a1),"r"(a2),"r"(a3), "r"(b0),"r"(b1));
            }
        }
        if (ch + 3 < NCHUNK) issue(ch + 3, (ch + 3) & (NSTAGE-1));
        asm volatile("cp.async.commit_group;" ::: "memory");  // empty group in tail keeps count
    }

    // epilogue: m16n8 fragment: acc[g][0,1] = (row lo, c0..c0+1), acc[g][2,3] = (row hi)
    int q = lane & 3;
    int r_lo = m0 + w*16 + (lane >> 2);
    const float* lgB = g_logu + (size_t)n*NPIX*CP;
    float* qaB = g_Qa + (size_t)n*NPIX*CP;

    #pragma unroll
    for (int half = 0; half < 2; half++) {
        int row = r_lo + half*8;
        int rowc = min(row, NPIX-1);
        const float* lg = lgB + (size_t)rowc*CP;
        float lt[6];
        #pragma unroll
        for (int g = 0; g < 3; g++) {
            int c0 = 8*g + 2*q;
            float2 l2 = *(const float2*)(lg + c0);
            lt[2*g]   = (c0   < NCH) ? l2.x + acc[g][half*2]   : -1e30f;
            lt[2*g+1] = (c0+1 < NCH) ? l2.y + acc[g][half*2+1] : -1e30f;
        }
        float mx = lt[0];
        #pragma unroll
        for (int i = 1; i < 6; i++) mx = fmaxf(mx, lt[i]);
        mx = fmaxf(mx, __shfl_xor_sync(0xffffffffu, mx, 1));
        mx = fmaxf(mx, __shfl_xor_sync(0xffffffffu, mx, 2));
        float e[6], s = 0.f;
        #pragma unroll
        for (int i = 0; i < 6; i++) { e[i] = __expf(lt[i]-mx); s += e[i]; }
        s += __shfl_xor_sync(0xffffffffu, s, 1);
        s += __shfl_xor_sync(0xffffffffu, s, 2);
        float inv = 1.0f/s;
        if (row < NPIX) {
            float* o = qaB + (size_t)row*CP;
            #pragma unroll
            for (int g = 0; g < 3; g++) {
                int c0 = 8*g + 2*q;
                float p0 = e[2*g]*inv, p1 = e[2*g+1]*inv;
                *(float2*)(o + c0) = make_float2(p0, p1);
                if (c0 < NCH) {
                    unsigned int b;
                    asm("cvt.rn.bf16x2.f32 %0, %1, %2;" : "=r"(b) : "f"(p1), "f"(p0));
                    Qo[(size_t)c0*KPAD + row] = (unsigned short)(b & 0xffffu);
                    if (c0 + 1 < NCH)
                        Qo[(size_t)(c0+1)*KPAD + row] = (unsigned short)(b >> 16);
                }
            }
        }
    }
}

// ---------------- loss ----------------
__global__ void k_loss1() {
    int tid = threadIdx.x;
    float part = 0.f;
    for (int t = blockIdx.x*256 + tid; t < NBATCH*NPIX; t += NLB*256) {
        const float* q  = g_Qa    + (size_t)t*CP;
        const float* pr = g_probs + (size_t)t*CP;
        float ps[NCH];
        float s = 0.f;
        #pragma unroll
        for (int c = 0; c < NCH; c++) { ps[c] = fmaxf(q[c], EPSV); s += ps[c]; }
        float inv = 1.0f/s;
        #pragma unroll
        for (int c = 0; c < NCH; c++) {
            float p = ps[c]*inv;
            float r = p/pr[c];
            r = fminf(fmaxf(r, 0.05f), 20.0f);
            part += p*__logf(r);
        }
    }
    for (int o = 16; o; o >>= 1) part += __shfl_down_sync(0xffffffffu, part, o);
    __shared__ float red[8];
    int wid = tid >> 5, lane = tid & 31;
    if (lane == 0) red[wid] = part;
    __syncthreads();
    if (wid == 0) {
        float v = (lane < 8) ? red[lane] : 0.f;
        for (int o = 4; o; o >>= 1) v += __shfl_down_sync(0xffffffffu, v, o);
        if (lane == 0) g_lpart[blockIdx.x] = v;
    }
}

__global__ void k_loss2(float* __restrict__ out) {
    int lane = threadIdx.x;   // 64 threads
    float v = g_lpart[lane];
    for (int o = 16; o; o >>= 1) v += __shfl_down_sync(0xffffffffu, v, o);
    __shared__ float red[2];
    if ((lane & 31) == 0) red[lane >> 5] = v;
    __syncthreads();
    if (lane == 0) out[0] = (red[0] + red[1]) / (float)(NBATCH*NPIX);
}

extern "C" void kernel_launch(void* const* d_in, const int* in_sizes, int n_in,
                              void* d_out, int out_size) {
    const float* images  = (const float*)d_in[0];
    const float* predict = (const float*)d_in[1];
    if (n_in >= 2 && in_sizes[0] < in_sizes[1]) {
        const float* tmp = images; images = predict; predict = tmp;
    }

    const int SMEM = NSTAGE*(TM + 24)*ASTR*2;   // 50688 B
    cudaFuncSetAttribute(k_mma, cudaFuncAttributeMaxDynamicSharedMemorySize, SMEM);

    k_rsg<<<(NPIX + 255)/256, 256>>>();
    k_resize<<<(NBATCH*NPIX + 127)/128, 128>>>(images);
    k_qzero<<<(int)(((size_t)2*NBATCH*32*KPAD/8 + 255)/256), 256>>>();
    k_probs<<<(NBATCH*NPIX + 127)/128, 128>>>(predict);
    k_sums<<<dim3((NPIX + 3)/4, NBATCH), 256>>>();
    k_keff<<<dim3((KPAD/2 + 255)/256, MPAD/TI, NBATCH), 256>>>();
    for (int it = 0; it < NITERS; it++) {
        k_mma<<<dim3(MPAD/TM, NBATCH), 128, SMEM>>>(it & 1);
    }
    k_loss1<<<NLB, 256>>>();
    k_loss2<<<1, 64>>>((float*)d_out);
}

// round 16
// speedup vs baseline: 5.7058x; 1.0093x over previous
#include <cuda_runtime.h>
#include <cuda_bf16.h>
#include <math.h>
#include <stdint.h>

#define H_IN 321
#define W_IN 321
#define WS 41
#define NPIX 1681
#define NCH 21
#define CP 24
#define NBATCH 16
#define NITERS 10

#define INVSC (321.0f/41.0f)
#define AG 8.0f                 /* 1/(2*(3/12)^2) */
#define ABF 0.011250f           /* 1/(2*(80/12)^2) */
#define BBF (1.0f/338.0f)       /* 1/(2*13^2) */
#define CG 3.0f
#define CB 10.0f
#define EPSV 1e-5f

#define KPAD 1728               /* 27*64: padded k extent of K and Qcm */
#define MPAD 1792               /* 28*64: padded row extent of K */
#define NCHUNK 27
#define TI 16                   /* keff i-tile */
#define NLB 64
#define ASTR 72                 /* padded smem row stride (bf16 elems), 72*2=144B */
#define TM 64                   /* k_mma row tile */
#define NSTAGE 6                /* cp.async pipeline depth (5 chunks in flight) */

__device__ __forceinline__ int div41(int j) { return (j*51151) >> 21; }

// ---------------- static device buffers ----------------
static __device__ float  g_colors[NBATCH*NPIX*4];
static __device__ float2 g_pos[NPIX];
static __device__ float  g_rsg[NPIX];
static __device__ float  g_rsb[NBATCH*NPIX];
static __device__ float  g_probs[NBATCH*NPIX*CP];
static __device__ float  g_logu[NBATCH*NPIX*CP];
static __device__ float  g_Qa[NBATCH*NPIX*CP];            // row-major fp32 Q (for loss)
static __device__ float  g_lpart[NLB];
static __device__ unsigned short g_Kh[(size_t)NBATCH*MPAD*KPAD];      // bf16 Keff, zero-padded
static __device__ unsigned short g_Qcm[(size_t)2*NBATCH*32*KPAD];     // bf16 Q channel-major x2

__device__ __forceinline__ uint32_t s2u(const void* p) {
    uint32_t a;
    asm("{ .reg .u64 t; cvta.to.shared.u64 t, %1; cvt.u32.u64 %0, t; }" : "=r"(a) : "l"(p));
    return a;
}
__device__ __forceinline__ void cp16(uint32_t dst, const void* src) {
    asm volatile("cp.async.cg.shared.global [%0], [%1], 16;" :: "r"(dst), "l"(src));
}

// ---------------- setup ----------------

__global__ void k_rsg() {
    int i = blockIdx.x*blockDim.x + threadIdx.x;
    if (i >= NPIX) return;
    int y = div41(i), x = i - y*41;
    g_pos[i] = make_float2((float)x, (float)y);
    float Sx = 0.f, Sy = 0.f;
    for (int j = 0; j < WS; j++) {
        int dx = x - j; Sx += expf(-AG * (float)(dx*dx));
        int dy = y - j; Sy += expf(-AG * (float)(dy*dy));
    }
    g_rsg[i] = rsqrtf(Sx*Sy - 1.0f);
}

__global__ void k_resize(const float* __restrict__ img) {
    int t = blockIdx.x*blockDim.x + threadIdx.x;
    if (t >= NBATCH*NPIX) return;
    int n = t / NPIX, p = t - n*NPIX;
    int oy = div41(p), ox = p - oy*41;

    float wy[18], wx[18];
    float sy = (oy + 0.5f)*INVSC - 0.5f;
    int jy0 = max(0, (int)ceilf(sy - INVSC));
    int jy1 = min(H_IN-1, (int)floorf(sy + INVSC));
    float sumy = 0.f;
    for (int j = jy0; j <= jy1; j++) {
        float w = fmaxf(1.0f - fabsf(sy - (float)j)*(1.0f/INVSC), 0.f);
        wy[j-jy0] = w; sumy += w;
    }
    float sx = (ox + 0.5f)*INVSC - 0.5f;
    int jx0 = max(0, (int)ceilf(sx - INVSC));
    int jx1 = min(W_IN-1, (int)floorf(sx + INVSC));
    float sumx = 0.f;
    for (int j = jx0; j <= jx1; j++) {
        float w = fmaxf(1.0f - fabsf(sx - (float)j)*(1.0f/INVSC), 0.f);
        wx[j-jx0] = w; sumx += w;
    }

    float a0 = 0.f, a1 = 0.f, a2 = 0.f;
    const float* b0 = img + (size_t)(n*3 + 0)*H_IN*W_IN;
    const float* b1 = img + (size_t)(n*3 + 1)*H_IN*W_IN;
    const float* b2 = img + (size_t)(n*3 + 2)*H_IN*W_IN;
    for (int jy = jy0; jy <= jy1; jy++) {
        float wyv = wy[jy-jy0];
        const float* r0 = b0 + (size_t)jy*W_IN;
        const float* r1 = b1 + (size_t)jy*W_IN;
        const float* r2 = b2 + (size_t)jy*W_IN;
        for (int jx = jx0; jx <= jx1; jx++) {
            float w = wyv * wx[jx-jx0];
            a0 = fmaf(w, r0[jx], a0);
            a1 = fmaf(w, r1[jx], a1);
            a2 = fmaf(w, r2[jx], a2);
        }
    }
    float inv = 1.0f/(sumy*sumx);
    float4 c; c.x = a0*inv; c.y = a1*inv; c.z = a2*inv; c.w = 0.f;
    ((float4*)g_colors)[t] = c;
}

// zero both Qcm buffers (pads stay zero through the run)
__global__ void k_qzero() {
    size_t t = (size_t)blockIdx.x*256 + threadIdx.x;
    size_t tot = (size_t)2*NBATCH*32*KPAD/8;
    if (t < tot) ((uint4*)g_Qcm)[t] = make_uint4(0,0,0,0);
}

__global__ void k_probs(const float* __restrict__ pred) {
    int t = blockIdx.x*blockDim.x + threadIdx.x;
    if (t >= NBATCH*NPIX) return;
    int n = t / NPIX, p = t - n*NPIX;
    const float* base = pred + (size_t)n*NCH*NPIX + p;
    float x[NCH];
    float m = -1e30f;
    #pragma unroll
    for (int c = 0; c < NCH; c++) { x[c] = base[(size_t)c*NPIX]; m = fmaxf(m, x[c]); }
    float s = 0.f;
    #pragma unroll
    for (int c = 0; c < NCH; c++) { x[c] = __expf(x[c]-m); s += x[c]; }
    float inv = 1.0f/s;
    float s2 = 0.f;
    #pragma unroll
    for (int c = 0; c < NCH; c++) { x[c] = fminf(fmaxf(x[c]*inv, EPSV), 1.0f); s2 += x[c]; }
    float inv2 = 1.0f/s2;
    float* pp = g_probs + (size_t)t*CP;
    float* pl = g_logu  + (size_t)t*CP;
    unsigned short* qc = g_Qcm + (size_t)n*32*KPAD;   // buffer 0
    #pragma unroll
    for (int c = 0; c < NCH; c++) {
        float v = x[c]*inv2;
        pp[c] = v; pl[c] = __logf(v);
        unsigned int b;
        asm("cvt.rn.bf16x2.f32 %0, %1, %2;" : "=r"(b) : "f"(0.f), "f"(v));
        qc[(size_t)c*KPAD + p] = (unsigned short)(b & 0xffffu);
    }
    #pragma unroll
    for (int c = NCH; c < CP; c++) { pp[c] = 0.f; pl[c] = 0.f; }
}

// bilateral row sums, i-tiled x4 (R14 exact)
__global__ void __launch_bounds__(256) k_sums() {
    int n = blockIdx.y;
    int i0 = blockIdx.x*4;
    int tid = threadIdx.x;
    const float4* cols = ((const float4*)g_colors) + (size_t)n*NPIX;
    float4 ci[4]; float2 pi[4];
    #pragma unroll
    for (int ii = 0; ii < 4; ii++) {
        int i = min(i0 + ii, NPIX-1);
        ci[ii] = cols[i]; pi[ii] = g_pos[i];
    }
    float sum[4] = {0.f, 0.f, 0.f, 0.f};
    for (int j = tid; j < NPIX; j += 256) {
        float2 pj = g_pos[j];
        float4 cj = cols[j];
        #pragma unroll
        for (int ii = 0; ii < 4; ii++) {
            float dy = pi[ii].y - pj.y, dx = pi[ii].x - pj.x;
            float dr = ci[ii].x - cj.x, dg = ci[ii].y - cj.y, db = ci[ii].z - cj.z;
            float d2 = fmaf(dy, dy, dx*dx);
            float cd2 = fmaf(dr, dr, fmaf(dg, dg, db*db));
            sum[ii] += __expf(fmaf(-ABF, d2, -BBF*cd2));
        }
    }
    __shared__ float red[4][8];
    int wid = tid >> 5, lane = tid & 31;
    #pragma unroll
    for (int ii = 0; ii < 4; ii++) {
        float v = sum[ii];
        for (int o = 16; o; o >>= 1) v += __shfl_down_sync(0xffffffffu, v, o);
        if (lane == 0) red[ii][wid] = v;
    }
    __syncthreads();
    if (tid < 4) {
        float v = 0.f;
        #pragma unroll
        for (int w = 0; w < 8; w++) v += red[tid][w];
        int i = i0 + tid;
        if (i < NPIX) g_rsb[n*NPIX + i] = rsqrtf(v - 1.0f);  // self term exp(0)=1
    }
}

// Keff = 10*Kb_norm + 3*Kg_norm, diag 0; bf16; i-tiled x16; kg gated (R14 exact math)
__global__ void __launch_bounds__(256) k_keff() {
    __shared__ float4 Ci[TI];
    __shared__ float2 Pi[TI];
    __shared__ float  Rb[TI], Rg[TI];
    int n = blockIdx.z;
    int i0 = blockIdx.y*TI;
    int jp = blockIdx.x*256 + threadIdx.x;   // pair index
    const float4* cols = ((const float4*)g_colors) + (size_t)n*NPIX;
    if (threadIdx.x < TI) {
        int ii = min(i0 + threadIdx.x, NPIX-1);
        Ci[threadIdx.x] = cols[ii];
        Pi[threadIdx.x] = g_pos[ii];
        Rb[threadIdx.x] = g_rsb[n*NPIX + ii];
        Rg[threadIdx.x] = g_rsg[ii];
    }
    __syncthreads();
    if (jp >= KPAD/2) return;
    int j0 = 2*jp, j1 = j0 + 1;
    int j0c = min(j0, NPIX-1), j1c = min(j1, NPIX-1);
    float4 cA = cols[j0c], cB = cols[j1c];
    float2 pA = g_pos[j0c], pB = g_pos[j1c];
    float rbA = g_rsb[n*NPIX+j0c], rbB = g_rsb[n*NPIX+j1c];
    float rgA = g_rsg[j0c], rgB = g_rsg[j1c];
    unsigned int* out = (unsigned int*)(g_Kh + ((size_t)n*MPAD + i0)*KPAD) + jp;
    #pragma unroll 4
    for (int ii = 0; ii < TI; ii++) {
        int i = i0 + ii;
        float4 ci = Ci[ii]; float2 pi = Pi[ii];
        float rbi = Rb[ii], rgi = Rg[ii];
        float v0 = 0.f, v1 = 0.f;
        if (i < NPIX) {
            {
                float dy = pi.y - pA.y, dx = pi.x - pA.x;
                float dr = ci.x - cA.x, dg = ci.y - cA.y, db = ci.z - cA.z;
                float d2 = fmaf(dy, dy, dx*dx);
                float cd2 = fmaf(dr, dr, fmaf(dg, dg, db*db));
                v0 = CB * __expf(fmaf(-ABF, d2, -BBF*cd2)) * rbi * rbA;
                if (d2 < 12.5f) v0 = fmaf(CG, __expf(-AG*d2)*rgi*rgA, v0);
                if (j0 >= NPIX || j0 == i) v0 = 0.f;
            }
            {
                float dy = pi.y - pB.y, dx = pi.x - pB.x;
                float dr = ci.x - cB.x, dg = ci.y - cB.y, db = ci.z - cB.z;
                float d2 = fmaf(dy, dy, dx*dx);
                float cd2 = fmaf(dr, dr, fmaf(dg, dg, db*db));
                v1 = CB * __expf(fmaf(-ABF, d2, -BBF*cd2)) * rbi * rbB;
                if (d2 < 12.5f) v1 = fmaf(CG, __expf(-AG*d2)*rgi*rgB, v1);
                if (j1 >= NPIX || j1 == i) v1 = 0.f;
            }
        }
        unsigned int pk;
        asm("cvt.rn.bf16x2.f32 %0, %1, %2;" : "=r"(pk) : "f"(v1), "f"(v0));
        out[(size_t)ii*(KPAD/2)] = pk;
    }
}

// ---------------- fused msg GEMM (mma.sync bf16, cp.async 6-stage) ----------------
// block: 128 thr = 4 warps; tile 64 rows x 24 ch; warp = 16 rows; grid 28x16=448.
// Pipeline: prologue stages 0..4; per iter: wait_group(4), sync, compute, issue ch+5.
__global__ void __launch_bounds__(128) k_mma(int dir) {
    extern __shared__ unsigned short sm[];
    unsigned short* As = sm;                       // NSTAGE x TM x ASTR
    unsigned short* Bs = sm + NSTAGE*TM*ASTR;      // NSTAGE x 24 x ASTR
    int tid = threadIdx.x;
    int lane = tid & 31, w = tid >> 5;
    int n = blockIdx.y, m0 = blockIdx.x*TM;
    const unsigned short* Kn = g_Kh + ((size_t)n*MPAD + m0)*KPAD;
    const unsigned short* Qc = g_Qcm + ((size_t)dir*NBATCH + n)*32*KPAD;
    unsigned short*       Qo = g_Qcm + ((size_t)(dir^1)*NBATCH + n)*32*KPAD;

    uint32_t asBase = s2u(As), bsBase = s2u(Bs);

    // issue chunk ch into stage buffer b
    auto issue = [&](int ch, int b) {
        uint32_t Ad = asBase + (uint32_t)(b*TM*ASTR*2);
        uint32_t Bd = bsBase + (uint32_t)(b*24*ASTR*2);
        const unsigned short* Ks = Kn + ch*64;
        const unsigned short* Qs = Qc + ch*64;
        #pragma unroll
        for (int r = 0; r < 4; r++) {                 // A: 64 rows x 8 x 16B = 512
            int u = tid + 128*r, row = u >> 3, g = u & 7;
            cp16(Ad + (uint32_t)((row*ASTR + g*8)*2), Ks + (size_t)row*KPAD + g*8);
        }
        {                                             // B: 24 rows x 8 x 16B = 192
            int u = tid, row = u >> 3, g = u & 7;
            cp16(Bd + (uint32_t)((row*ASTR + g*8)*2), Qs + (size_t)row*KPAD + g*8);
            u = tid + 128;
            if (u < 192) {
                row = u >> 3; g = u & 7;
                cp16(Bd + (uint32_t)((row*ASTR + g*8)*2), Qs + (size_t)row*KPAD + g*8);
            }
        }
    };

    float acc[3][4];
    #pragma unroll
    for (int g = 0; g < 3; g++)
        #pragma unroll
        for (int i = 0; i < 4; i++) acc[g][i] = 0.f;

    // prologue: 5 stages in flight
    #pragma unroll
    for (int s = 0; s < NSTAGE-1; s++) {
        issue(s, s);
        asm volatile("cp.async.commit_group;" ::: "memory");
    }

    int b = 0;       // stage of chunk ch (mod NSTAGE, tracked incrementally)
    int bn = NSTAGE-1; // stage of chunk ch+NSTAGE-1
    for (int ch = 0; ch < NCHUNK; ch++) {
        asm volatile("cp.async.wait_group %0;" :: "n"(NSTAGE-2) : "memory");
        __syncthreads();
        uint32_t Ab = asBase + (uint32_t)(b*TM*ASTR*2);
        uint32_t Bb = bsBase + (uint32_t)(b*24*ASTR*2);
        #pragma unroll
        for (int kk = 0; kk < 4; kk++) {
            uint32_t a0,a1,a2,a3;
            uint32_t aaddr = Ab + (uint32_t)(((w*16 + (lane & 15))*ASTR + kk*16 + (lane >> 4)*8)*2);
            asm volatile("ldmatrix.sync.aligned.m8n8.x4.shared.b16 {%0,%1,%2,%3}, [%4];"
                         : "=r"(a0),"=r"(a1),"=r"(a2),"=r"(a3) : "r"(aaddr));
            #pragma unroll
            for (int g = 0; g < 3; g++) {
                uint32_t b0,b1;
                uint32_t baddr = Bb + (uint32_t)((((g*8 + (lane>>2)))*ASTR + kk*16 + (lane&3)*2)*2);
                asm volatile("ld.shared.b32 %0, [%1];" : "=r"(b0) : "r"(baddr));
                asm volatile("ld.shared.b32 %0, [%1];" : "=r"(b1) : "r"(baddr + 16));
                asm volatile("mma.sync.aligned.m16n8k16.row.col.f32.bf16.bf16.f32 "
                             "{%0,%1,%2,%3}, {%4,%5,%6,%7}, {%8,%9}, {%0,%1,%2,%3};"
                             : "+f"(acc[g][0]),"+f"(acc[g][1]),"+f"(acc[g][2]),"+f"(acc[g][3])
                             : "r"(a0),"r"(a1),"r"(a2),"r"(a3), "r"(b0),"r"(b1));
            }
        }
        if (ch + NSTAGE-1 < NCHUNK) issue(ch + NSTAGE-1, bn);
        asm volatile("cp.async.commit_group;" ::: "memory");  // empty group in tail keeps count
        if (++b == NSTAGE) b = 0;
        if (++bn == NSTAGE) bn = 0;
    }

    // epilogue: m16n8 fragment: acc[g][0,1] = (row lo, c0..c0+1), acc[g][2,3] = (row hi)
    int q = lane & 3;
    int r_lo = m0 + w*16 + (lane >> 2);
    const float* lgB = g_logu + (size_t)n*NPIX*CP;
    float* qaB = g_Qa + (size_t)n*NPIX*CP;

    #pragma unroll
    for (int half = 0; half < 2; half++) {
        int row = r_lo + half*8;
        int rowc = min(row, NPIX-1);
        const float* lg = lgB + (size_t)rowc*CP;
        float lt[6];
        #pragma unroll
        for (int g = 0; g < 3; g++) {
            int c0 = 8*g + 2*q;
            float2 l2 = *(const float2*)(lg + c0);
            lt[2*g]   = (c0   < NCH) ? l2.x + acc[g][half*2]   : -1e30f;
            lt[2*g+1] = (c0+1 < NCH) ? l2.y + acc[g][half*2+1] : -1e30f;
        }
        float mx = lt[0];
        #pragma unroll
        for (int i = 1; i < 6; i++) mx = fmaxf(mx, lt[i]);
        mx = fmaxf(mx, __shfl_xor_sync(0xffffffffu, mx, 1));
        mx = fmaxf(mx, __shfl_xor_sync(0xffffffffu, mx, 2));
        float e[6], s = 0.f;
        #pragma unroll
        for (int i = 0; i < 6; i++) { e[i] = __expf(lt[i]-mx); s += e[i]; }
        s += __shfl_xor_sync(0xffffffffu, s, 1);
        s += __shfl_xor_sync(0xffffffffu, s, 2);
        float inv = 1.0f/s;
        if (row < NPIX) {
            float* o = qaB + (size_t)row*CP;
            #pragma unroll
            for (int g = 0; g < 3; g++) {
                int c0 = 8*g + 2*q;
                float p0 = e[2*g]*inv, p1 = e[2*g+1]*inv;
                *(float2*)(o + c0) = make_float2(p0, p1);
                if (c0 < NCH) {
                    unsigned int b2;
                    asm("cvt.rn.bf16x2.f32 %0, %1, %2;" : "=r"(b2) : "f"(p1), "f"(p0));
                    Qo[(size_t)c0*KPAD + row] = (unsigned short)(b2 & 0xffffu);
                    if (c0 + 1 < NCH)
                        Qo[(size_t)(c0+1)*KPAD + row] = (unsigned short)(b2 >> 16);
                }
            }
        }
    }
}

// ---------------- loss ----------------
__global__ void k_loss1() {
    int tid = threadIdx.x;
    float part = 0.f;
    for (int t = blockIdx.x*256 + tid; t < NBATCH*NPIX; t += NLB*256) {
        const float* q  = g_Qa    + (size_t)t*CP;
        const float* pr = g_probs + (size_t)t*CP;
        float ps[NCH];
        float s = 0.f;
        #pragma unroll
        for (int c = 0; c < NCH; c++) { ps[c] = fmaxf(q[c], EPSV); s += ps[c]; }
        float inv = 1.0f/s;
        #pragma unroll
        for (int c = 0; c < NCH; c++) {
            float p = ps[c]*inv;
            float r = p/pr[c];
            r = fminf(fmaxf(r, 0.05f), 20.0f);
            part += p*__logf(r);
        }
    }
    for (int o = 16; o; o >>= 1) part += __shfl_down_sync(0xffffffffu, part, o);
    __shared__ float red[8];
    int wid = tid >> 5, lane = tid & 31;
    if (lane == 0) red[wid] = part;
    __syncthreads();
    if (wid == 0) {
        float v = (lane < 8) ? red[lane] : 0.f;
        for (int o = 4; o; o >>= 1) v += __shfl_down_sync(0xffffffffu, v, o);
        if (lane == 0) g_lpart[blockIdx.x] = v;
    }
}

__global__ void k_loss2(float* __restrict__ out) {
    int lane = threadIdx.x;   // 64 threads
    float v = g_lpart[lane];
    for (int o = 16; o; o >>= 1) v += __shfl_down_sync(0xffffffffu, v, o);
    __shared__ float red[2];
    if ((lane & 31) == 0) red[lane >> 5] = v;
    __syncthreads();
    if (lane == 0) out[0] = (red[0] + red[1]) / (float)(NBATCH*NPIX);
}

extern "C" void kernel_launch(void* const* d_in, const int* in_sizes, int n_in,
                              void* d_out, int out_size) {
    const float* images  = (const float*)d_in[0];
    const float* predict = (const float*)d_in[1];
    if (n_in >= 2 && in_sizes[0] < in_sizes[1]) {
        const float* tmp = images; images = predict; predict = tmp;
    }

    const int SMEM = NSTAGE*(TM + 24)*ASTR*2;   // 76032 B
    cudaFuncSetAttribute(k_mma, cudaFuncAttributeMaxDynamicSharedMemorySize, SMEM);

    k_rsg<<<(NPIX + 255)/256, 256>>>();
    k_resize<<<(NBATCH*NPIX + 127)/128, 128>>>(images);
    k_qzero<<<(int)(((size_t)2*NBATCH*32*KPAD/8 + 255)/256), 256>>>();
    k_probs<<<(NBATCH*NPIX + 127)/128, 128>>>(predict);
    k_sums<<<dim3((NPIX + 3)/4, NBATCH), 256>>>();
    k_keff<<<dim3((KPAD/2 + 255)/256, (NPIX + TI - 1)/TI, NBATCH), 256>>>();
    for (int it = 0; it < NITERS; it++) {
        k_mma<<<dim3(MPAD/TM, NBATCH), 128, SMEM>>>(it & 1);
    }
    k_loss1<<<NLB, 256>>>();
    k_loss2<<<1, 64>>>((float*)d_out);
}